// round 1
// baseline (speedup 1.0000x reference)
#include <cuda_runtime.h>

#define NMAX 100000
#define EMAX 1600000
#define TMAX (NMAX + EMAX)

// ---------------- scratch (static device globals; no allocation) ----------------
__device__ int    g_deg[NMAX];
__device__ int    g_rowptr[NMAX + 1];
__device__ int    g_cursor[NMAX];
__device__ int    g_csrc[TMAX];

__device__ float  g_h1[NMAX * 128];   // layer1 pre-attention features (x @ W1)
__device__ float4 g_as1[NMAX];        // alpha_src per node, 4 heads
__device__ float4 g_ad1[NMAX];        // alpha_dst per node, 4 heads
__device__ float4 g_m1[NMAX];         // segment max per node/head
__device__ float4 g_r1[NMAX];         // 1/(denom+eps)
__device__ float4 g_alpha1[TMAX];     // softmax weight per CSR entry, 4 heads

__device__ float  g_h1a[NMAX * 128];  // relu(agg1 + b1): layer2 input
__device__ float  g_h2[NMAX * 32];    // layer2 pre-attention features
__device__ float  g_as2[NMAX];
__device__ float  g_ad2[NMAX];
__device__ float  g_m2[NMAX];
__device__ float  g_r2[NMAX];
__device__ float  g_alpha2[TMAX];

__device__ __forceinline__ float lrelu(float x) { return x > 0.f ? x : 0.2f * x; }

// ---------------- CSR build ----------------
__global__ void initdeg_kernel(int N) {
    int n = blockIdx.x * blockDim.x + threadIdx.x;
    if (n < N) g_deg[n] = 1;  // self loop
}

__global__ void hist_kernel(const int* __restrict__ ei, int E) {
    int e = blockIdx.x * blockDim.x + threadIdx.x;
    if (e < E) atomicAdd(&g_deg[ei[E + e]], 1);
}

__global__ void scan_kernel(int N) {
    __shared__ int s[1024];
    int t = threadIdx.x;
    int chunk = (N + 1023) >> 10;
    int lo = t * chunk;
    int hi = min(lo + chunk, N);
    int sum = 0;
    for (int i = lo; i < hi; i++) sum += g_deg[i];
    s[t] = sum;
    __syncthreads();
    for (int off = 1; off < 1024; off <<= 1) {
        int v = (t >= off) ? s[t - off] : 0;
        __syncthreads();
        s[t] += v;
        __syncthreads();
    }
    int run = (t > 0) ? s[t - 1] : 0;
    for (int i = lo; i < hi; i++) { g_rowptr[i] = run; run += g_deg[i]; }
    if (t == 1023) g_rowptr[N] = s[1023];
}

__global__ void fillself_kernel(int N) {
    int n = blockIdx.x * blockDim.x + threadIdx.x;
    if (n < N) {
        int r = g_rowptr[n];
        g_csrc[r] = n;         // self loop first
        g_cursor[n] = r + 1;
    }
}

__global__ void filledge_kernel(const int* __restrict__ ei, int E) {
    int e = blockIdx.x * blockDim.x + threadIdx.x;
    if (e < E) {
        int dst = ei[E + e];
        int pos = atomicAdd(&g_cursor[dst], 1);
        g_csrc[pos] = ei[e];
    }
}

// ---------------- GEMM: Y[N,M] = X[N,K] @ W[K,M] (fp32, smem-tiled) ----------------
template <int K, int M, int NB, int TPB>
__global__ void gemm_kernel(const float* __restrict__ X, const float* __restrict__ W,
                            float* __restrict__ Y, int N) {
    constexpr int G  = M / 4;        // column groups of 4
    constexpr int NT = TPB / G;      // thread groups along nodes
    constexpr int TN = NT * NB;      // nodes per block
    constexpr int XSTR = K + (G < 32 ? 1 : 0);  // pad when ty varies inside a warp

    __shared__ float Ws[K * M];
    __shared__ float xs[TN * XSTR];

    int t  = threadIdx.x;
    int tx = t % G;
    int ty = t / G;
    int n0 = blockIdx.x * TN;

    constexpr int WF = (K * M) / 4 / TPB;
#pragma unroll
    for (int r = 0; r < WF; r++) {
        int f = t + r * TPB;
        ((float4*)Ws)[f] = ((const float4*)W)[f];
    }
    constexpr int XF = (TN * K) / 4 / TPB;
#pragma unroll
    for (int r = 0; r < XF; r++) {
        int f = t + r * TPB;
        int node = f / (K / 4);
        int kk   = (f % (K / 4)) * 4;
        int gn = n0 + node;
        float4 v = make_float4(0.f, 0.f, 0.f, 0.f);
        if (gn < N) v = *(const float4*)&X[(size_t)gn * K + kk];
        float* dst = &xs[node * XSTR + kk];
        dst[0] = v.x; dst[1] = v.y; dst[2] = v.z; dst[3] = v.w;
    }
    __syncthreads();

    float4 acc[NB];
#pragma unroll
    for (int b = 0; b < NB; b++) acc[b] = make_float4(0.f, 0.f, 0.f, 0.f);

#pragma unroll 8
    for (int k = 0; k < K; k++) {
        float4 w = *(const float4*)&Ws[k * M + tx * 4];
#pragma unroll
        for (int b = 0; b < NB; b++) {
            float xv = xs[(ty * NB + b) * XSTR + k];
            acc[b].x += xv * w.x;
            acc[b].y += xv * w.y;
            acc[b].z += xv * w.z;
            acc[b].w += xv * w.w;
        }
    }
#pragma unroll
    for (int b = 0; b < NB; b++) {
        int gn = n0 + ty * NB + b;
        if (gn < N) *(float4*)&Y[(size_t)gn * M + tx * 4] = acc[b];
    }
}

// ---------------- layer 1: attention coefficients ----------------
__global__ void coef1_kernel(const float* __restrict__ a_src, const float* __restrict__ a_dst, int N) {
    int n = (blockIdx.x * blockDim.x + threadIdx.x) >> 5;
    int lane = threadIdx.x & 31;
    if (n >= N) return;
    float ps[4], pd[4];
#pragma unroll
    for (int h = 0; h < 4; h++) {
        float v = g_h1[(size_t)n * 128 + h * 32 + lane];
        ps[h] = v * a_src[h * 32 + lane];
        pd[h] = v * a_dst[h * 32 + lane];
    }
#pragma unroll
    for (int off = 16; off > 0; off >>= 1) {
#pragma unroll
        for (int h = 0; h < 4; h++) {
            ps[h] += __shfl_xor_sync(0xffffffffu, ps[h], off);
            pd[h] += __shfl_xor_sync(0xffffffffu, pd[h], off);
        }
    }
    if (lane == 0) {
        g_as1[n] = make_float4(ps[0], ps[1], ps[2], ps[3]);
        g_ad1[n] = make_float4(pd[0], pd[1], pd[2], pd[3]);
    }
}

// ---------------- layer 1: softmax stats (online max + denom) ----------------
__global__ void stats1_kernel(int N) {
    int n = (blockIdx.x * blockDim.x + threadIdx.x) >> 5;
    int lane = threadIdx.x & 31;
    if (n >= N) return;
    float4 ad = g_ad1[n];
    float adv[4] = {ad.x, ad.y, ad.z, ad.w};
    float m[4] = {-1e30f, -1e30f, -1e30f, -1e30f};
    float d[4] = {0.f, 0.f, 0.f, 0.f};
    int beg = g_rowptr[n], end = g_rowptr[n + 1];
    for (int i = beg + lane; i < end; i += 32) {
        int s = g_csrc[i];
        float4 as = g_as1[s];
        float e[4] = {lrelu(as.x + adv[0]), lrelu(as.y + adv[1]),
                      lrelu(as.z + adv[2]), lrelu(as.w + adv[3])};
#pragma unroll
        for (int h = 0; h < 4; h++) {
            if (e[h] > m[h]) { d[h] = d[h] * __expf(m[h] - e[h]) + 1.f; m[h] = e[h]; }
            else             { d[h] += __expf(e[h] - m[h]); }
        }
    }
#pragma unroll
    for (int off = 16; off > 0; off >>= 1) {
#pragma unroll
        for (int h = 0; h < 4; h++) {
            float om = __shfl_xor_sync(0xffffffffu, m[h], off);
            float od = __shfl_xor_sync(0xffffffffu, d[h], off);
            float nm = fmaxf(m[h], om);
            d[h] = d[h] * __expf(m[h] - nm) + od * __expf(om - nm);
            m[h] = nm;
        }
    }
    if (lane == 0) {
        g_m1[n] = make_float4(m[0], m[1], m[2], m[3]);
        g_r1[n] = make_float4(1.f / (d[0] + 1e-16f), 1.f / (d[1] + 1e-16f),
                              1.f / (d[2] + 1e-16f), 1.f / (d[3] + 1e-16f));
    }
}

// ---------------- layer 1: per-edge alpha ----------------
__global__ void alpha1_kernel(int N) {
    int n = (blockIdx.x * blockDim.x + threadIdx.x) >> 5;
    int lane = threadIdx.x & 31;
    if (n >= N) return;
    float4 ad = g_ad1[n];
    float4 m  = g_m1[n];
    float4 r  = g_r1[n];
    int beg = g_rowptr[n], end = g_rowptr[n + 1];
    for (int i = beg + lane; i < end; i += 32) {
        int s = g_csrc[i];
        float4 as = g_as1[s];
        float4 a;
        a.x = __expf(lrelu(as.x + ad.x) - m.x) * r.x;
        a.y = __expf(lrelu(as.y + ad.y) - m.y) * r.y;
        a.z = __expf(lrelu(as.z + ad.z) - m.z) * r.z;
        a.w = __expf(lrelu(as.w + ad.w) - m.w) * r.w;
        g_alpha1[i] = a;
    }
}

// ---------------- layer 1: aggregation + bias + relu ----------------
__global__ void agg1_kernel(const float* __restrict__ b1, int N) {
    int n = (blockIdx.x * blockDim.x + threadIdx.x) >> 5;
    int lane = threadIdx.x & 31;
    if (n >= N) return;
    int beg = g_rowptr[n], end = g_rowptr[n + 1];
    float a0 = 0.f, a1 = 0.f, a2 = 0.f, a3 = 0.f;
    int i = beg;
    for (; i + 4 <= end; i += 4) {
        int s0 = g_csrc[i], s1 = g_csrc[i + 1], s2 = g_csrc[i + 2], s3 = g_csrc[i + 3];
        float4 w0 = g_alpha1[i], w1 = g_alpha1[i + 1], w2 = g_alpha1[i + 2], w3 = g_alpha1[i + 3];
        const float* p0 = g_h1 + (size_t)s0 * 128 + lane;
        const float* p1 = g_h1 + (size_t)s1 * 128 + lane;
        const float* p2 = g_h1 + (size_t)s2 * 128 + lane;
        const float* p3 = g_h1 + (size_t)s3 * 128 + lane;
        a0 += w0.x * p0[0]  + w1.x * p1[0]  + w2.x * p2[0]  + w3.x * p3[0];
        a1 += w0.y * p0[32] + w1.y * p1[32] + w2.y * p2[32] + w3.y * p3[32];
        a2 += w0.z * p0[64] + w1.z * p1[64] + w2.z * p2[64] + w3.z * p3[64];
        a3 += w0.w * p0[96] + w1.w * p1[96] + w2.w * p2[96] + w3.w * p3[96];
    }
    for (; i < end; i++) {
        int s = g_csrc[i];
        float4 w = g_alpha1[i];
        const float* p = g_h1 + (size_t)s * 128 + lane;
        a0 += w.x * p[0];
        a1 += w.y * p[32];
        a2 += w.z * p[64];
        a3 += w.w * p[96];
    }
    size_t o = (size_t)n * 128 + lane;
    g_h1a[o]      = fmaxf(a0 + b1[lane],      0.f);
    g_h1a[o + 32] = fmaxf(a1 + b1[lane + 32], 0.f);
    g_h1a[o + 64] = fmaxf(a2 + b1[lane + 64], 0.f);
    g_h1a[o + 96] = fmaxf(a3 + b1[lane + 96], 0.f);
}

// ---------------- layer 2: coefficients ----------------
__global__ void coef2_kernel(const float* __restrict__ a_src, const float* __restrict__ a_dst, int N) {
    int n = (blockIdx.x * blockDim.x + threadIdx.x) >> 5;
    int lane = threadIdx.x & 31;
    if (n >= N) return;
    float v = g_h2[(size_t)n * 32 + lane];
    float ps = v * a_src[lane];
    float pd = v * a_dst[lane];
#pragma unroll
    for (int off = 16; off > 0; off >>= 1) {
        ps += __shfl_xor_sync(0xffffffffu, ps, off);
        pd += __shfl_xor_sync(0xffffffffu, pd, off);
    }
    if (lane == 0) { g_as2[n] = ps; g_ad2[n] = pd; }
}

__global__ void stats2_kernel(int N) {
    int n = (blockIdx.x * blockDim.x + threadIdx.x) >> 5;
    int lane = threadIdx.x & 31;
    if (n >= N) return;
    float ad = g_ad2[n];
    float m = -1e30f, d = 0.f;
    int beg = g_rowptr[n], end = g_rowptr[n + 1];
    for (int i = beg + lane; i < end; i += 32) {
        float e = lrelu(g_as2[g_csrc[i]] + ad);
        if (e > m) { d = d * __expf(m - e) + 1.f; m = e; }
        else       { d += __expf(e - m); }
    }
#pragma unroll
    for (int off = 16; off > 0; off >>= 1) {
        float om = __shfl_xor_sync(0xffffffffu, m, off);
        float od = __shfl_xor_sync(0xffffffffu, d, off);
        float nm = fmaxf(m, om);
        d = d * __expf(m - nm) + od * __expf(om - nm);
        m = nm;
    }
    if (lane == 0) { g_m2[n] = m; g_r2[n] = 1.f / (d + 1e-16f); }
}

__global__ void alpha2_kernel(int N) {
    int n = (blockIdx.x * blockDim.x + threadIdx.x) >> 5;
    int lane = threadIdx.x & 31;
    if (n >= N) return;
    float ad = g_ad2[n];
    float m = g_m2[n];
    float r = g_r2[n];
    int beg = g_rowptr[n], end = g_rowptr[n + 1];
    for (int i = beg + lane; i < end; i += 32) {
        g_alpha2[i] = __expf(lrelu(g_as2[g_csrc[i]] + ad) - m) * r;
    }
}

// ---------------- layer 2 aggregation + bias + relu + final linear ----------------
__global__ void agg2_kernel(const float* __restrict__ b2, const float* __restrict__ Wl,
                            const float* __restrict__ bl, float* __restrict__ out, int N) {
    int n = (blockIdx.x * blockDim.x + threadIdx.x) >> 5;
    int lane = threadIdx.x & 31;
    if (n >= N) return;
    int beg = g_rowptr[n], end = g_rowptr[n + 1];
    float acc = 0.f;
    int i = beg;
    for (; i + 4 <= end; i += 4) {
        int s0 = g_csrc[i], s1 = g_csrc[i + 1], s2 = g_csrc[i + 2], s3 = g_csrc[i + 3];
        float w0 = g_alpha2[i], w1 = g_alpha2[i + 1], w2 = g_alpha2[i + 2], w3 = g_alpha2[i + 3];
        acc += w0 * g_h2[(size_t)s0 * 32 + lane];
        acc += w1 * g_h2[(size_t)s1 * 32 + lane];
        acc += w2 * g_h2[(size_t)s2 * 32 + lane];
        acc += w3 * g_h2[(size_t)s3 * 32 + lane];
    }
    for (; i < end; i++) {
        acc += g_alpha2[i] * g_h2[(size_t)g_csrc[i] * 32 + lane];
    }
    float v = fmaxf(acc + b2[lane], 0.f) * Wl[lane];
#pragma unroll
    for (int off = 16; off > 0; off >>= 1) v += __shfl_xor_sync(0xffffffffu, v, off);
    if (lane == 0) out[n] = v + bl[0];
}

// ---------------- launch ----------------
extern "C" void kernel_launch(void* const* d_in, const int* in_sizes, int n_in,
                              void* d_out, int out_size) {
    const float* x    = (const float*)d_in[0];
    const int*   ei   = (const int*)d_in[1];
    // d_in[2] = batch (unused)
    const float* W1   = (const float*)d_in[3];
    const float* as1w = (const float*)d_in[4];
    const float* ad1w = (const float*)d_in[5];
    const float* b1   = (const float*)d_in[6];
    const float* W2   = (const float*)d_in[7];
    const float* as2w = (const float*)d_in[8];
    const float* ad2w = (const float*)d_in[9];
    const float* b2   = (const float*)d_in[10];
    const float* Wl   = (const float*)d_in[11];
    const float* bl   = (const float*)d_in[12];
    float* out = (float*)d_out;

    int N = in_sizes[0] / 64;
    int E = in_sizes[1] / 2;

    float *h1p, *h1ap, *h2p;
    cudaGetSymbolAddress((void**)&h1p,  g_h1);
    cudaGetSymbolAddress((void**)&h1ap, g_h1a);
    cudaGetSymbolAddress((void**)&h2p,  g_h2);

    int nb = (N + 255) / 256;
    int eb = (E + 255) / 256;
    int wb = (N + 7) / 8;  // 8 warps per 256-thread block, warp-per-node

    // CSR build
    initdeg_kernel<<<nb, 256>>>(N);
    hist_kernel<<<eb, 256>>>(ei, E);
    scan_kernel<<<1, 1024>>>(N);
    fillself_kernel<<<nb, 256>>>(N);
    filledge_kernel<<<eb, 256>>>(ei, E);

    // layer 1
    gemm_kernel<64, 128, 8, 256><<<(N + 63) / 64, 256>>>(x, W1, h1p, N);
    coef1_kernel<<<wb, 256>>>(as1w, ad1w, N);
    stats1_kernel<<<wb, 256>>>(N);
    alpha1_kernel<<<wb, 256>>>(N);
    agg1_kernel<<<wb, 256>>>(b1, N);

    // layer 2
    gemm_kernel<128, 32, 2, 128><<<(N + 31) / 32, 128>>>(h1ap, W2, h2p, N);
    coef2_kernel<<<wb, 256>>>(as2w, ad2w, N);
    stats2_kernel<<<wb, 256>>>(N);
    alpha2_kernel<<<wb, 256>>>(N);
    agg2_kernel<<<wb, 256>>>(b2, Wl, bl, out, N);
}

// round 2
// speedup vs baseline: 1.1313x; 1.1313x over previous
#include <cuda_runtime.h>

#define NMAX 100000
#define EMAX 1600000
#define TMAX (NMAX + EMAX)

// ---------------- scratch (static device globals; no allocation) ----------------
__device__ int    g_deg[NMAX];
__device__ int    g_rowptr[NMAX + 1];
__device__ int    g_cursor[NMAX];
__device__ int    g_csrc[TMAX];

__device__ float  g_h1[NMAX * 128];   // layer1 pre-attention features (x @ W1)
__device__ float4 g_as1[NMAX];        // h . a_src per node, 4 heads
__device__ float4 g_ad1[NMAX];        // h . a_dst per node, 4 heads

__device__ float  g_h1a[NMAX * 128];  // relu(agg1 + b1): layer2 input
__device__ float  g_h2[NMAX * 32];    // layer2 pre-attention features
__device__ float  g_as2[NMAX];
__device__ float  g_ad2[NMAX];

__device__ __forceinline__ float lrelu(float x) { return x > 0.f ? x : 0.2f * x; }

// ---------------- CSR build ----------------
__global__ void initdeg_kernel(int N) {
    int n = blockIdx.x * blockDim.x + threadIdx.x;
    if (n < N) g_deg[n] = 1;  // self loop
}

__global__ void hist_kernel(const int* __restrict__ ei, int E) {
    int e = blockIdx.x * blockDim.x + threadIdx.x;
    if (e < E) atomicAdd(&g_deg[ei[E + e]], 1);
}

__global__ void scan_kernel(int N) {
    __shared__ int s[1024];
    int t = threadIdx.x;
    int chunk = (N + 1023) >> 10;
    int lo = t * chunk;
    int hi = min(lo + chunk, N);
    int sum = 0;
    for (int i = lo; i < hi; i++) sum += g_deg[i];
    s[t] = sum;
    __syncthreads();
    for (int off = 1; off < 1024; off <<= 1) {
        int v = (t >= off) ? s[t - off] : 0;
        __syncthreads();
        s[t] += v;
        __syncthreads();
    }
    int run = (t > 0) ? s[t - 1] : 0;
    for (int i = lo; i < hi; i++) { g_rowptr[i] = run; run += g_deg[i]; }
    if (t == 1023) g_rowptr[N] = s[1023];
}

__global__ void fillself_kernel(int N) {
    int n = blockIdx.x * blockDim.x + threadIdx.x;
    if (n < N) {
        int r = g_rowptr[n];
        g_csrc[r] = n;         // self loop first
        g_cursor[n] = r + 1;
    }
}

__global__ void filledge_kernel(const int* __restrict__ ei, int E) {
    int e = blockIdx.x * blockDim.x + threadIdx.x;
    if (e < E) {
        int dst = ei[E + e];
        int pos = atomicAdd(&g_cursor[dst], 1);
        g_csrc[pos] = ei[e];
    }
}

// ---------------- GEMM1: h1[N,128] = X[N,64] @ W1[64,128] + coef epilogue ----------------
// TPB=256, 64 nodes/block. Thread (tx,ty): cols 4tx..4tx+3, nodes ty*8..ty*8+7.
__global__ void __launch_bounds__(256) gemm1_kernel(
    const float* __restrict__ X, const float* __restrict__ W,
    const float* __restrict__ a_src, const float* __restrict__ a_dst,
    float* __restrict__ Y, int N) {
    __shared__ float Ws[64 * 128];
    __shared__ float xs[64 * 64];

    int t  = threadIdx.x;
    int tx = t & 31;
    int ty = t >> 5;
    int n0 = blockIdx.x * 64;

#pragma unroll
    for (int r = 0; r < 8; r++)
        ((float4*)Ws)[t + r * 256] = ((const float4*)W)[t + r * 256];
#pragma unroll
    for (int r = 0; r < 4; r++) {
        int f = t + r * 256;
        int node = f >> 4;
        int kk = (f & 15) << 2;
        int gn = n0 + node;
        float4 v = make_float4(0.f, 0.f, 0.f, 0.f);
        if (gn < N) v = *(const float4*)&X[(size_t)gn * 64 + kk];
        *(float4*)&xs[node * 64 + kk] = v;
    }
    __syncthreads();

    float4 acc[8];
#pragma unroll
    for (int b = 0; b < 8; b++) acc[b] = make_float4(0.f, 0.f, 0.f, 0.f);

#pragma unroll 4
    for (int k0 = 0; k0 < 64; k0 += 4) {
        float4 w0 = *(const float4*)&Ws[(k0 + 0) * 128 + tx * 4];
        float4 w1 = *(const float4*)&Ws[(k0 + 1) * 128 + tx * 4];
        float4 w2 = *(const float4*)&Ws[(k0 + 2) * 128 + tx * 4];
        float4 w3 = *(const float4*)&Ws[(k0 + 3) * 128 + tx * 4];
#pragma unroll
        for (int b = 0; b < 8; b++) {
            float4 xv = *(const float4*)&xs[(ty * 8 + b) * 64 + k0];
            acc[b].x += xv.x * w0.x + xv.y * w1.x + xv.z * w2.x + xv.w * w3.x;
            acc[b].y += xv.x * w0.y + xv.y * w1.y + xv.z * w2.y + xv.w * w3.y;
            acc[b].z += xv.x * w0.z + xv.y * w1.z + xv.z * w2.z + xv.w * w3.z;
            acc[b].w += xv.x * w0.w + xv.y * w1.w + xv.z * w2.w + xv.w * w3.w;
        }
    }

    float4 av = ((const float4*)a_src)[tx];
    float4 dv = ((const float4*)a_dst)[tx];
    float* asf = (float*)g_as1;
    float* adf = (float*)g_ad1;
    int h = tx >> 3;
#pragma unroll
    for (int b = 0; b < 8; b++) {
        int gn = n0 + ty * 8 + b;
        float ps = acc[b].x * av.x + acc[b].y * av.y + acc[b].z * av.z + acc[b].w * av.w;
        float pd = acc[b].x * dv.x + acc[b].y * dv.y + acc[b].z * dv.z + acc[b].w * dv.w;
#pragma unroll
        for (int off = 4; off > 0; off >>= 1) {
            ps += __shfl_xor_sync(0xffffffffu, ps, off);
            pd += __shfl_xor_sync(0xffffffffu, pd, off);
        }
        if (gn < N) {
            *(float4*)&Y[(size_t)gn * 128 + tx * 4] = acc[b];
            if ((tx & 7) == 0) {
                asf[gn * 4 + h] = ps;
                adf[gn * 4 + h] = pd;
            }
        }
    }
}

// ---------------- GEMM2: h2[N,32] = h1a[N,128] @ W2[128,32] + coef epilogue ----------------
// TPB=128, 32 nodes/block. Thread (tx<8, ty<16): cols 4tx..4tx+3, nodes ty*2..ty*2+1.
__global__ void __launch_bounds__(128) gemm2_kernel(
    const float* __restrict__ X, const float* __restrict__ W,
    const float* __restrict__ a_src, const float* __restrict__ a_dst,
    float* __restrict__ Y, int N) {
    __shared__ float Ws[128 * 32];
    __shared__ float xs[32 * 132];

    int t  = threadIdx.x;
    int tx = t & 7;
    int ty = t >> 3;
    int n0 = blockIdx.x * 32;

#pragma unroll
    for (int r = 0; r < 8; r++)
        ((float4*)Ws)[t + r * 128] = ((const float4*)W)[t + r * 128];
#pragma unroll
    for (int r = 0; r < 8; r++) {
        int f = t + r * 128;
        int node = f >> 5;
        int kk = (f & 31) << 2;
        int gn = n0 + node;
        float4 v = make_float4(0.f, 0.f, 0.f, 0.f);
        if (gn < N) v = *(const float4*)&X[(size_t)gn * 128 + kk];
        *(float4*)&xs[node * 132 + kk] = v;
    }
    __syncthreads();

    float4 acc[2];
    acc[0] = make_float4(0.f, 0.f, 0.f, 0.f);
    acc[1] = make_float4(0.f, 0.f, 0.f, 0.f);

#pragma unroll 4
    for (int k0 = 0; k0 < 128; k0 += 4) {
        float4 w0 = *(const float4*)&Ws[(k0 + 0) * 32 + tx * 4];
        float4 w1 = *(const float4*)&Ws[(k0 + 1) * 32 + tx * 4];
        float4 w2 = *(const float4*)&Ws[(k0 + 2) * 32 + tx * 4];
        float4 w3 = *(const float4*)&Ws[(k0 + 3) * 32 + tx * 4];
#pragma unroll
        for (int b = 0; b < 2; b++) {
            float4 xv = *(const float4*)&xs[(ty * 2 + b) * 132 + k0];
            acc[b].x += xv.x * w0.x + xv.y * w1.x + xv.z * w2.x + xv.w * w3.x;
            acc[b].y += xv.x * w0.y + xv.y * w1.y + xv.z * w2.y + xv.w * w3.y;
            acc[b].z += xv.x * w0.z + xv.y * w1.z + xv.z * w2.z + xv.w * w3.z;
            acc[b].w += xv.x * w0.w + xv.y * w1.w + xv.z * w2.w + xv.w * w3.w;
        }
    }

    float4 av = ((const float4*)a_src)[tx];
    float4 dv = ((const float4*)a_dst)[tx];
#pragma unroll
    for (int b = 0; b < 2; b++) {
        int gn = n0 + ty * 2 + b;
        float ps = acc[b].x * av.x + acc[b].y * av.y + acc[b].z * av.z + acc[b].w * av.w;
        float pd = acc[b].x * dv.x + acc[b].y * dv.y + acc[b].z * dv.z + acc[b].w * dv.w;
#pragma unroll
        for (int off = 4; off > 0; off >>= 1) {
            ps += __shfl_xor_sync(0xffffffffu, ps, off);
            pd += __shfl_xor_sync(0xffffffffu, pd, off);
        }
        if (gn < N) {
            *(float4*)&Y[(size_t)gn * 32 + tx * 4] = acc[b];
            if (tx == 0) {
                g_as2[gn] = ps;
                g_ad2[gn] = pd;
            }
        }
    }
}

// ---------------- layer 1: fused softmax + aggregation + bias + relu ----------------
// warp per node; unnormalized w = exp(lrelu(as[src]+ad[dst])), divide by sum at end.
__global__ void agg1_kernel(const float* __restrict__ b1, int N) {
    int n = (blockIdx.x * blockDim.x + threadIdx.x) >> 5;
    int lane = threadIdx.x & 31;
    if (n >= N) return;
    const float* asf = (const float*)g_as1;
    float4 adv4 = g_ad1[n];
    float adv[4] = {adv4.x, adv4.y, adv4.z, adv4.w};
    int beg = g_rowptr[n], end = g_rowptr[n + 1];
    int j  = lane & 3;
    int h4 = (lane >> 2) & 3;

    float a0 = 0.f, a1 = 0.f, a2 = 0.f, a3 = 0.f;
    float d0 = 0.f, d1 = 0.f, d2 = 0.f, d3 = 0.f;

    for (int i = beg; i < end; i += 4) {
        int cnt = end - i;
        int s_l = 0;
        if (lane < 4 && lane < cnt) s_l = g_csrc[i + lane];
        int s0 = __shfl_sync(0xffffffffu, s_l, 0);
        int s1 = __shfl_sync(0xffffffffu, s_l, 1);
        int s2 = __shfl_sync(0xffffffffu, s_l, 2);
        int s3 = __shfl_sync(0xffffffffu, s_l, 3);
        int sj = __shfl_sync(0xffffffffu, s_l, j);

        float w = __expf(lrelu(asf[(size_t)sj * 4 + h4] + adv[h4]));
        if (j >= cnt) w = 0.f;

        float w00 = __shfl_sync(0xffffffffu, w, 0);
        float w01 = __shfl_sync(0xffffffffu, w, 1);
        float w02 = __shfl_sync(0xffffffffu, w, 2);
        float w03 = __shfl_sync(0xffffffffu, w, 3);
        float w10 = __shfl_sync(0xffffffffu, w, 4);
        float w11 = __shfl_sync(0xffffffffu, w, 5);
        float w12 = __shfl_sync(0xffffffffu, w, 6);
        float w13 = __shfl_sync(0xffffffffu, w, 7);
        float w20 = __shfl_sync(0xffffffffu, w, 8);
        float w21 = __shfl_sync(0xffffffffu, w, 9);
        float w22 = __shfl_sync(0xffffffffu, w, 10);
        float w23 = __shfl_sync(0xffffffffu, w, 11);
        float w30 = __shfl_sync(0xffffffffu, w, 12);
        float w31 = __shfl_sync(0xffffffffu, w, 13);
        float w32 = __shfl_sync(0xffffffffu, w, 14);
        float w33 = __shfl_sync(0xffffffffu, w, 15);

        const float* p0 = g_h1 + (size_t)s0 * 128 + lane;
        const float* p1 = g_h1 + (size_t)s1 * 128 + lane;
        const float* p2 = g_h1 + (size_t)s2 * 128 + lane;
        const float* p3 = g_h1 + (size_t)s3 * 128 + lane;

        a0 += w00 * p0[0]  + w01 * p1[0]  + w02 * p2[0]  + w03 * p3[0];
        a1 += w10 * p0[32] + w11 * p1[32] + w12 * p2[32] + w13 * p3[32];
        a2 += w20 * p0[64] + w21 * p1[64] + w22 * p2[64] + w23 * p3[64];
        a3 += w30 * p0[96] + w31 * p1[96] + w32 * p2[96] + w33 * p3[96];
        d0 += w00 + w01 + w02 + w03;
        d1 += w10 + w11 + w12 + w13;
        d2 += w20 + w21 + w22 + w23;
        d3 += w30 + w31 + w32 + w33;
    }

    size_t o = (size_t)n * 128 + lane;
    g_h1a[o]      = fmaxf(a0 / d0 + b1[lane],      0.f);
    g_h1a[o + 32] = fmaxf(a1 / d1 + b1[lane + 32], 0.f);
    g_h1a[o + 64] = fmaxf(a2 / d2 + b1[lane + 64], 0.f);
    g_h1a[o + 96] = fmaxf(a3 / d3 + b1[lane + 96], 0.f);
}

// ---------------- layer 2: fused softmax + aggregation + bias + relu + final linear ----------------
__global__ void agg2_kernel(const float* __restrict__ b2, const float* __restrict__ Wl,
                            const float* __restrict__ bl, float* __restrict__ out, int N) {
    int n = (blockIdx.x * blockDim.x + threadIdx.x) >> 5;
    int lane = threadIdx.x & 31;
    if (n >= N) return;
    float ad = g_ad2[n];
    int beg = g_rowptr[n], end = g_rowptr[n + 1];
    int j = lane & 3;

    float acc = 0.f, ds = 0.f;
    for (int i = beg; i < end; i += 4) {
        int cnt = end - i;
        int s_l = 0;
        if (lane < 4 && lane < cnt) s_l = g_csrc[i + lane];
        int s0 = __shfl_sync(0xffffffffu, s_l, 0);
        int s1 = __shfl_sync(0xffffffffu, s_l, 1);
        int s2 = __shfl_sync(0xffffffffu, s_l, 2);
        int s3 = __shfl_sync(0xffffffffu, s_l, 3);
        int sj = __shfl_sync(0xffffffffu, s_l, j);

        float w = __expf(lrelu(g_as2[sj] + ad));
        if (j >= cnt) w = 0.f;

        float w0 = __shfl_sync(0xffffffffu, w, 0);
        float w1 = __shfl_sync(0xffffffffu, w, 1);
        float w2 = __shfl_sync(0xffffffffu, w, 2);
        float w3 = __shfl_sync(0xffffffffu, w, 3);

        acc += w0 * g_h2[(size_t)s0 * 32 + lane];
        acc += w1 * g_h2[(size_t)s1 * 32 + lane];
        acc += w2 * g_h2[(size_t)s2 * 32 + lane];
        acc += w3 * g_h2[(size_t)s3 * 32 + lane];
        ds  += w0 + w1 + w2 + w3;
    }

    float v = fmaxf(acc / ds + b2[lane], 0.f) * Wl[lane];
#pragma unroll
    for (int off = 16; off > 0; off >>= 1) v += __shfl_xor_sync(0xffffffffu, v, off);
    if (lane == 0) out[n] = v + bl[0];
}

// ---------------- launch ----------------
extern "C" void kernel_launch(void* const* d_in, const int* in_sizes, int n_in,
                              void* d_out, int out_size) {
    const float* x    = (const float*)d_in[0];
    const int*   ei   = (const int*)d_in[1];
    const float* W1   = (const float*)d_in[3];
    const float* as1w = (const float*)d_in[4];
    const float* ad1w = (const float*)d_in[5];
    const float* b1   = (const float*)d_in[6];
    const float* W2   = (const float*)d_in[7];
    const float* as2w = (const float*)d_in[8];
    const float* ad2w = (const float*)d_in[9];
    const float* b2   = (const float*)d_in[10];
    const float* Wl   = (const float*)d_in[11];
    const float* bl   = (const float*)d_in[12];
    float* out = (float*)d_out;

    int N = in_sizes[0] / 64;
    int E = in_sizes[1] / 2;

    float *h1p, *h1ap, *h2p;
    cudaGetSymbolAddress((void**)&h1p,  g_h1);
    cudaGetSymbolAddress((void**)&h1ap, g_h1a);
    cudaGetSymbolAddress((void**)&h2p,  g_h2);

    int nb = (N + 255) / 256;
    int eb = (E + 255) / 256;
    int wb = (N + 7) / 8;  // warp-per-node, 8 warps per 256-thread block

    // CSR build
    initdeg_kernel<<<nb, 256>>>(N);
    hist_kernel<<<eb, 256>>>(ei, E);
    scan_kernel<<<1, 1024>>>(N);
    fillself_kernel<<<nb, 256>>>(N);
    filledge_kernel<<<eb, 256>>>(ei, E);

    // layer 1
    gemm1_kernel<<<(N + 63) / 64, 256>>>(x, W1, as1w, ad1w, h1p, N);
    agg1_kernel<<<wb, 256>>>(b1, N);

    // layer 2
    gemm2_kernel<<<(N + 31) / 32, 128>>>(h1ap, W2, as2w, ad2w, h2p, N);
    agg2_kernel<<<wb, 256>>>(b2, Wl, bl, out, N);
}

// round 4
// speedup vs baseline: 1.2759x; 1.1278x over previous
#include <cuda_runtime.h>
#include <cuda_fp16.h>

#define NMAX 100000
#define EMAX 1600000
#define TMAX (NMAX + EMAX)

// ---------------- scratch (static device globals; no allocation) ----------------
__device__ int    g_deg[NMAX];
__device__ int    g_rowptr[NMAX + 1];
__device__ int    g_cursor[NMAX];
__device__ int    g_csrc[TMAX];

__device__ __half2 g_h1h[NMAX * 64];   // layer1 features (x@W1), 128ch as 64 half2
__device__ float4  g_as1[NMAX];        // h . a_src per node, 4 heads
__device__ float4  g_ad1[NMAX];        // h . a_dst per node, 4 heads

__device__ __half2 g_h1ah[NMAX * 64];  // relu(agg1 + b1): layer2 input, half2
__device__ float   g_h2[NMAX * 32];    // layer2 pre-attention features (fp32)
__device__ float   g_as2[NMAX];
__device__ float   g_ad2[NMAX];

__device__ __forceinline__ float lrelu(float x) { return x > 0.f ? x : 0.2f * x; }

// ---------------- CSR build ----------------
__global__ void initdeg_kernel(int N) {
    int n = blockIdx.x * blockDim.x + threadIdx.x;
    if (n < N) g_deg[n] = 1;  // self loop
}

__global__ void hist_kernel(const int* __restrict__ ei, int E) {
    int e = blockIdx.x * blockDim.x + threadIdx.x;
    if (e < E) atomicAdd(&g_deg[ei[E + e]], 1);
}

__global__ void scan_kernel(int N) {
    __shared__ int s[1024];
    int t = threadIdx.x;
    int chunk = (N + 1023) >> 10;
    int lo = t * chunk;
    int hi = min(lo + chunk, N);
    int sum = 0;
    for (int i = lo; i < hi; i++) sum += g_deg[i];
    s[t] = sum;
    __syncthreads();
    for (int off = 1; off < 1024; off <<= 1) {
        int v = (t >= off) ? s[t - off] : 0;
        __syncthreads();
        s[t] += v;
        __syncthreads();
    }
    int run = (t > 0) ? s[t - 1] : 0;
    for (int i = lo; i < hi; i++) { g_rowptr[i] = run; run += g_deg[i]; }
    if (t == 1023) g_rowptr[N] = s[1023];
}

__global__ void fillself_kernel(int N) {
    int n = blockIdx.x * blockDim.x + threadIdx.x;
    if (n < N) {
        int r = g_rowptr[n];
        g_csrc[r] = n;         // self loop first
        g_cursor[n] = r + 1;
    }
}

__global__ void filledge_kernel(const int* __restrict__ ei, int E) {
    int e = blockIdx.x * blockDim.x + threadIdx.x;
    if (e < E) {
        int dst = ei[E + e];
        int pos = atomicAdd(&g_cursor[dst], 1);
        g_csrc[pos] = ei[e];
    }
}

// ---------------- GEMM1: h1[N,128] = X[N,64] @ W1[64,128] + coef epilogue ----------------
// TPB=256, 64 nodes/block. Thread (tx,ty): cols 4tx..4tx+3, nodes ty*8..ty*8+7.
__global__ void __launch_bounds__(256) gemm1_kernel(
    const float* __restrict__ X, const float* __restrict__ W,
    const float* __restrict__ a_src, const float* __restrict__ a_dst, int N) {
    __shared__ float Ws[64 * 128];
    __shared__ float xs[64 * 64];

    int t  = threadIdx.x;
    int tx = t & 31;
    int ty = t >> 5;
    int n0 = blockIdx.x * 64;

#pragma unroll
    for (int r = 0; r < 8; r++)
        ((float4*)Ws)[t + r * 256] = ((const float4*)W)[t + r * 256];
#pragma unroll
    for (int r = 0; r < 4; r++) {
        int f = t + r * 256;
        int node = f >> 4;
        int kk = (f & 15) << 2;
        int gn = n0 + node;
        float4 v = make_float4(0.f, 0.f, 0.f, 0.f);
        if (gn < N) v = *(const float4*)&X[(size_t)gn * 64 + kk];
        *(float4*)&xs[node * 64 + kk] = v;
    }
    __syncthreads();

    float4 acc[8];
#pragma unroll
    for (int b = 0; b < 8; b++) acc[b] = make_float4(0.f, 0.f, 0.f, 0.f);

#pragma unroll 4
    for (int k0 = 0; k0 < 64; k0 += 4) {
        float4 w0 = *(const float4*)&Ws[(k0 + 0) * 128 + tx * 4];
        float4 w1 = *(const float4*)&Ws[(k0 + 1) * 128 + tx * 4];
        float4 w2 = *(const float4*)&Ws[(k0 + 2) * 128 + tx * 4];
        float4 w3 = *(const float4*)&Ws[(k0 + 3) * 128 + tx * 4];
#pragma unroll
        for (int b = 0; b < 8; b++) {
            float4 xv = *(const float4*)&xs[(ty * 8 + b) * 64 + k0];
            acc[b].x += xv.x * w0.x + xv.y * w1.x + xv.z * w2.x + xv.w * w3.x;
            acc[b].y += xv.x * w0.y + xv.y * w1.y + xv.z * w2.y + xv.w * w3.y;
            acc[b].z += xv.x * w0.z + xv.y * w1.z + xv.z * w2.z + xv.w * w3.z;
            acc[b].w += xv.x * w0.w + xv.y * w1.w + xv.z * w2.w + xv.w * w3.w;
        }
    }

    float4 av = ((const float4*)a_src)[tx];
    float4 dv = ((const float4*)a_dst)[tx];
    float* asf = (float*)g_as1;
    float* adf = (float*)g_ad1;
    int h = tx >> 3;
#pragma unroll
    for (int b = 0; b < 8; b++) {
        int gn = n0 + ty * 8 + b;
        float ps = acc[b].x * av.x + acc[b].y * av.y + acc[b].z * av.z + acc[b].w * av.w;
        float pd = acc[b].x * dv.x + acc[b].y * dv.y + acc[b].z * dv.z + acc[b].w * dv.w;
#pragma unroll
        for (int off = 4; off > 0; off >>= 1) {
            ps += __shfl_xor_sync(0xffffffffu, ps, off);
            pd += __shfl_xor_sync(0xffffffffu, pd, off);
        }
        if (gn < N) {
            g_h1h[(size_t)gn * 64 + tx * 2]     = __floats2half2_rn(acc[b].x, acc[b].y);
            g_h1h[(size_t)gn * 64 + tx * 2 + 1] = __floats2half2_rn(acc[b].z, acc[b].w);
            if ((tx & 7) == 0) {
                asf[gn * 4 + h] = ps;
                adf[gn * 4 + h] = pd;
            }
        }
    }
}

// ---------------- layer 1: fused softmax + aggregation + bias + relu (half features) ----------------
// warp per node; lane owns channels {2l,2l+1} (head l>>4) and {64+2l,64+2l+1} (head 2+(l>>4)).
__global__ void agg1_kernel(const float* __restrict__ b1, int N) {
    int n = (blockIdx.x * blockDim.x + threadIdx.x) >> 5;
    int lane = threadIdx.x & 31;
    if (n >= N) return;
    const float* asf = (const float*)g_as1;
    const float* adf = (const float*)g_ad1;
    int e  = lane & 3;        // edge slot (lanes<16)
    int h  = lane >> 2;       // head slot (lanes<16)
    int hA = lane >> 4;       // head of first channel pair (0/1)
    float adh = (lane < 16) ? adf[(size_t)n * 4 + h] : 0.f;

    int beg = g_rowptr[n], end = g_rowptr[n + 1];
    float4 acc = make_float4(0.f, 0.f, 0.f, 0.f);
    float dsum = 0.f;

    for (int i = beg; i < end; i += 4) {
        int cnt = end - i;
        int s_l = 0;
        if (lane < 4 && lane < cnt) s_l = g_csrc[i + lane];
        int s0 = __shfl_sync(0xffffffffu, s_l, 0);
        int s1 = __shfl_sync(0xffffffffu, s_l, 1);
        int s2 = __shfl_sync(0xffffffffu, s_l, 2);
        int s3 = __shfl_sync(0xffffffffu, s_l, 3);

        float w = 0.f;
        if (lane < 16 && e < cnt) {
            int se = (e == 0) ? s0 : (e == 1) ? s1 : (e == 2) ? s2 : s3;
            w = __expf(lrelu(asf[(size_t)se * 4 + h] + adh));
        }
        dsum += w;

#define AGG1_EDGE(EI, SR)                                                       \
        {                                                                       \
            float wA = __shfl_sync(0xffffffffu, w, 4 * hA + EI);                \
            float wB = __shfl_sync(0xffffffffu, w, 8 + 4 * hA + EI);            \
            __half2 vA = g_h1h[(size_t)(SR) * 64 + lane];                       \
            __half2 vB = g_h1h[(size_t)(SR) * 64 + 32 + lane];                  \
            float2 fA = __half22float2(vA);                                     \
            float2 fB = __half22float2(vB);                                     \
            acc.x += wA * fA.x; acc.y += wA * fA.y;                             \
            acc.z += wB * fB.x; acc.w += wB * fB.y;                             \
        }
        AGG1_EDGE(0, s0)
        AGG1_EDGE(1, s1)
        AGG1_EDGE(2, s2)
        AGG1_EDGE(3, s3)
#undef AGG1_EDGE
    }

    // per-head denominators: sum over the 4 edge-slot lanes within each head group
    dsum += __shfl_xor_sync(0xffffffffu, dsum, 1);
    dsum += __shfl_xor_sync(0xffffffffu, dsum, 2);
    float dA = __shfl_sync(0xffffffffu, dsum, 4 * hA);
    float dB = __shfl_sync(0xffffffffu, dsum, 8 + 4 * hA);
    float rA = 1.f / dA;
    float rB = 1.f / dB;

    float o0 = fmaxf(acc.x * rA + b1[2 * lane],      0.f);
    float o1 = fmaxf(acc.y * rA + b1[2 * lane + 1],  0.f);
    float o2 = fmaxf(acc.z * rB + b1[64 + 2 * lane], 0.f);
    float o3 = fmaxf(acc.w * rB + b1[64 + 2 * lane + 1], 0.f);
    g_h1ah[(size_t)n * 64 + lane]      = __floats2half2_rn(o0, o1);
    g_h1ah[(size_t)n * 64 + 32 + lane] = __floats2half2_rn(o2, o3);
}

// ---------------- GEMM2: h2[N,32] = h1a[N,128](half) @ W2[128,32] + coef epilogue ----------------
// TPB=128, 32 nodes/block. Thread (tx<8, ty<16): cols 4tx..4tx+3, nodes ty*2..ty*2+1.
__global__ void __launch_bounds__(128) gemm2_kernel(
    const float* __restrict__ W,
    const float* __restrict__ a_src, const float* __restrict__ a_dst,
    float* __restrict__ Y, int N) {
    __shared__ float   Ws[128 * 32];
    __shared__ __half2 xs[32 * 68];   // 64 half2 per row, padded stride 68

    int t  = threadIdx.x;
    int tx = t & 7;
    int ty = t >> 3;
    int n0 = blockIdx.x * 32;

#pragma unroll
    for (int r = 0; r < 8; r++)
        ((float4*)Ws)[t + r * 128] = ((const float4*)W)[t + r * 128];
    // X rows: 64 half2 = 32 int2 each; 32 rows * 32 = 1024 int2, 8 per thread
#pragma unroll
    for (int r = 0; r < 8; r++) {
        int f = t + r * 128;
        int node = f >> 5;
        int part = f & 31;
        int gn = n0 + node;
        int2 v = make_int2(0, 0);
        if (gn < N) v = ((const int2*)g_h1ah)[(size_t)gn * 32 + part];
        *(int2*)&xs[node * 68 + part * 2] = v;
    }
    __syncthreads();

    float4 acc[2];
    acc[0] = make_float4(0.f, 0.f, 0.f, 0.f);
    acc[1] = make_float4(0.f, 0.f, 0.f, 0.f);

#pragma unroll 4
    for (int k0 = 0; k0 < 128; k0 += 4) {
        float4 w0 = *(const float4*)&Ws[(k0 + 0) * 32 + tx * 4];
        float4 w1 = *(const float4*)&Ws[(k0 + 1) * 32 + tx * 4];
        float4 w2 = *(const float4*)&Ws[(k0 + 2) * 32 + tx * 4];
        float4 w3 = *(const float4*)&Ws[(k0 + 3) * 32 + tx * 4];
#pragma unroll
        for (int b = 0; b < 2; b++) {
            int2 p = *(const int2*)&xs[(ty * 2 + b) * 68 + (k0 >> 1)];
            float2 x01 = __half22float2(*(__half2*)&p.x);
            float2 x23 = __half22float2(*(__half2*)&p.y);
            acc[b].x += x01.x * w0.x + x01.y * w1.x + x23.x * w2.x + x23.y * w3.x;
            acc[b].y += x01.x * w0.y + x01.y * w1.y + x23.x * w2.y + x23.y * w3.y;
            acc[b].z += x01.x * w0.z + x01.y * w1.z + x23.x * w2.z + x23.y * w3.z;
            acc[b].w += x01.x * w0.w + x01.y * w1.w + x23.x * w2.w + x23.y * w3.w;
        }
    }

    float4 av = ((const float4*)a_src)[tx];
    float4 dv = ((const float4*)a_dst)[tx];
#pragma unroll
    for (int b = 0; b < 2; b++) {
        int gn = n0 + ty * 2 + b;
        float ps = acc[b].x * av.x + acc[b].y * av.y + acc[b].z * av.z + acc[b].w * av.w;
        float pd = acc[b].x * dv.x + acc[b].y * dv.y + acc[b].z * dv.z + acc[b].w * dv.w;
#pragma unroll
        for (int off = 4; off > 0; off >>= 1) {
            ps += __shfl_xor_sync(0xffffffffu, ps, off);
            pd += __shfl_xor_sync(0xffffffffu, pd, off);
        }
        if (gn < N) {
            *(float4*)&Y[(size_t)gn * 32 + tx * 4] = acc[b];
            if (tx == 0) {
                g_as2[gn] = ps;
                g_ad2[gn] = pd;
            }
        }
    }
}

// ---------------- layer 2: fused softmax + aggregation + bias + relu + final linear ----------------
__global__ void agg2_kernel(const float* __restrict__ b2, const float* __restrict__ Wl,
                            const float* __restrict__ bl, float* __restrict__ out, int N) {
    int n = (blockIdx.x * blockDim.x + threadIdx.x) >> 5;
    int lane = threadIdx.x & 31;
    if (n >= N) return;
    float ad = g_ad2[n];
    int beg = g_rowptr[n], end = g_rowptr[n + 1];
    int j = lane & 3;

    float acc = 0.f, ds = 0.f;
    for (int i = beg; i < end; i += 4) {
        int cnt = end - i;
        int s_l = 0;
        if (lane < 4 && lane < cnt) s_l = g_csrc[i + lane];
        int s0 = __shfl_sync(0xffffffffu, s_l, 0);
        int s1 = __shfl_sync(0xffffffffu, s_l, 1);
        int s2 = __shfl_sync(0xffffffffu, s_l, 2);
        int s3 = __shfl_sync(0xffffffffu, s_l, 3);
        int sj = __shfl_sync(0xffffffffu, s_l, j);

        float w = 0.f;
        if (j < cnt) w = __expf(lrelu(g_as2[sj] + ad));

        float w0 = __shfl_sync(0xffffffffu, w, 0);
        float w1 = __shfl_sync(0xffffffffu, w, 1);
        float w2 = __shfl_sync(0xffffffffu, w, 2);
        float w3 = __shfl_sync(0xffffffffu, w, 3);

        acc += w0 * g_h2[(size_t)s0 * 32 + lane];
        acc += w1 * g_h2[(size_t)s1 * 32 + lane];
        acc += w2 * g_h2[(size_t)s2 * 32 + lane];
        acc += w3 * g_h2[(size_t)s3 * 32 + lane];
        ds  += w0 + w1 + w2 + w3;
    }

    float v = fmaxf(acc / ds + b2[lane], 0.f) * Wl[lane];
#pragma unroll
    for (int off = 16; off > 0; off >>= 1) v += __shfl_xor_sync(0xffffffffu, v, off);
    if (lane == 0) out[n] = v + bl[0];
}

// ---------------- launch ----------------
extern "C" void kernel_launch(void* const* d_in, const int* in_sizes, int n_in,
                              void* d_out, int out_size) {
    const float* x    = (const float*)d_in[0];
    const int*   ei   = (const int*)d_in[1];
    const float* W1   = (const float*)d_in[3];
    const float* as1w = (const float*)d_in[4];
    const float* ad1w = (const float*)d_in[5];
    const float* b1   = (const float*)d_in[6];
    const float* W2   = (const float*)d_in[7];
    const float* as2w = (const float*)d_in[8];
    const float* ad2w = (const float*)d_in[9];
    const float* b2   = (const float*)d_in[10];
    const float* Wl   = (const float*)d_in[11];
    const float* bl   = (const float*)d_in[12];
    float* out = (float*)d_out;

    int N = in_sizes[0] / 64;
    int E = in_sizes[1] / 2;

    float* h2p;
    cudaGetSymbolAddress((void**)&h2p, g_h2);

    int nb = (N + 255) / 256;
    int eb = (E + 255) / 256;
    int wb = (N + 7) / 8;  // warp-per-node, 8 warps per 256-thread block

    // CSR build
    initdeg_kernel<<<nb, 256>>>(N);
    hist_kernel<<<eb, 256>>>(ei, E);
    scan_kernel<<<1, 1024>>>(N);
    fillself_kernel<<<nb, 256>>>(N);
    filledge_kernel<<<eb, 256>>>(ei, E);

    // layer 1
    gemm1_kernel<<<(N + 63) / 64, 256>>>(x, W1, as1w, ad1w, N);
    agg1_kernel<<<wb, 256>>>(b1, N);

    // layer 2
    gemm2_kernel<<<(N + 31) / 32, 128>>>(W2, as2w, ad2w, h2p, N);
    agg2_kernel<<<wb, 256>>>(b2, Wl, bl, out, N);
}

// round 5
// speedup vs baseline: 1.3130x; 1.0291x over previous
#include <cuda_runtime.h>
#include <cuda_fp16.h>

#define NMAX 100000
#define EMAX 1600000
#define TMAX (NMAX + EMAX)

// ---------------- scratch (static device globals; no allocation) ----------------
__device__ int    g_deg[NMAX];
__device__ int    g_rowptr[NMAX + 1];
__device__ int    g_cursor[NMAX];
__device__ int    g_csrc[TMAX];

__device__ __half2 g_h1h[NMAX * 64];   // layer1 features (x@W1), 128ch as 64 half2
__device__ float4  g_as1[NMAX];        // h . a_src per node, 4 heads
__device__ float4  g_ad1[NMAX];        // h . a_dst per node, 4 heads

__device__ __half2 g_h1ah[NMAX * 64];  // relu(agg1 + b1): layer2 input, half2
__device__ __half2 g_h2h[NMAX * 16];   // layer2 pre-attention features, 32ch half2
__device__ float   g_as2[NMAX];
__device__ float   g_ad2[NMAX];

__device__ __forceinline__ float lrelu(float x) { return x > 0.f ? x : 0.2f * x; }

// ---------------- CSR build ----------------
__global__ void initdeg_kernel(int N) {
    int n = blockIdx.x * blockDim.x + threadIdx.x;
    if (n < N) g_deg[n] = 1;  // self loop
}

__global__ void hist_kernel(const int* __restrict__ ei, int E) {
    int e = blockIdx.x * blockDim.x + threadIdx.x;
    if (e < E) atomicAdd(&g_deg[ei[E + e]], 1);
}

__global__ void scan_kernel(int N) {
    __shared__ int s[1024];
    int t = threadIdx.x;
    int chunk = (N + 1023) >> 10;
    int lo = t * chunk;
    int hi = min(lo + chunk, N);
    int sum = 0;
    for (int i = lo; i < hi; i++) sum += g_deg[i];
    s[t] = sum;
    __syncthreads();
    for (int off = 1; off < 1024; off <<= 1) {
        int v = (t >= off) ? s[t - off] : 0;
        __syncthreads();
        s[t] += v;
        __syncthreads();
    }
    int run = (t > 0) ? s[t - 1] : 0;
    for (int i = lo; i < hi; i++) { g_rowptr[i] = run; run += g_deg[i]; }
    if (t == 1023) g_rowptr[N] = s[1023];
}

__global__ void fillself_kernel(int N) {
    int n = blockIdx.x * blockDim.x + threadIdx.x;
    if (n < N) {
        int r = g_rowptr[n];
        g_csrc[r] = n;         // self loop first
        g_cursor[n] = r + 1;
    }
}

__global__ void filledge_kernel(const int* __restrict__ ei, int E) {
    int e = blockIdx.x * blockDim.x + threadIdx.x;
    if (e < E) {
        int dst = ei[E + e];
        int pos = atomicAdd(&g_cursor[dst], 1);
        g_csrc[pos] = ei[e];
    }
}

// ---------------- GEMM1: h1[N,128] = X[N,64] @ W1[64,128] + coef epilogue ----------------
__global__ void __launch_bounds__(256) gemm1_kernel(
    const float* __restrict__ X, const float* __restrict__ W,
    const float* __restrict__ a_src, const float* __restrict__ a_dst, int N) {
    __shared__ float Ws[64 * 128];
    __shared__ float xs[64 * 64];

    int t  = threadIdx.x;
    int tx = t & 31;
    int ty = t >> 5;
    int n0 = blockIdx.x * 64;

#pragma unroll
    for (int r = 0; r < 8; r++)
        ((float4*)Ws)[t + r * 256] = ((const float4*)W)[t + r * 256];
#pragma unroll
    for (int r = 0; r < 4; r++) {
        int f = t + r * 256;
        int node = f >> 4;
        int kk = (f & 15) << 2;
        int gn = n0 + node;
        float4 v = make_float4(0.f, 0.f, 0.f, 0.f);
        if (gn < N) v = *(const float4*)&X[(size_t)gn * 64 + kk];
        *(float4*)&xs[node * 64 + kk] = v;
    }
    __syncthreads();

    float4 acc[8];
#pragma unroll
    for (int b = 0; b < 8; b++) acc[b] = make_float4(0.f, 0.f, 0.f, 0.f);

#pragma unroll 4
    for (int k0 = 0; k0 < 64; k0 += 4) {
        float4 w0 = *(const float4*)&Ws[(k0 + 0) * 128 + tx * 4];
        float4 w1 = *(const float4*)&Ws[(k0 + 1) * 128 + tx * 4];
        float4 w2 = *(const float4*)&Ws[(k0 + 2) * 128 + tx * 4];
        float4 w3 = *(const float4*)&Ws[(k0 + 3) * 128 + tx * 4];
#pragma unroll
        for (int b = 0; b < 8; b++) {
            float4 xv = *(const float4*)&xs[(ty * 8 + b) * 64 + k0];
            acc[b].x += xv.x * w0.x + xv.y * w1.x + xv.z * w2.x + xv.w * w3.x;
            acc[b].y += xv.x * w0.y + xv.y * w1.y + xv.z * w2.y + xv.w * w3.y;
            acc[b].z += xv.x * w0.z + xv.y * w1.z + xv.z * w2.z + xv.w * w3.z;
            acc[b].w += xv.x * w0.w + xv.y * w1.w + xv.z * w2.w + xv.w * w3.w;
        }
    }

    float4 av = ((const float4*)a_src)[tx];
    float4 dv = ((const float4*)a_dst)[tx];
    float* asf = (float*)g_as1;
    float* adf = (float*)g_ad1;
    int h = tx >> 3;
#pragma unroll
    for (int b = 0; b < 8; b++) {
        int gn = n0 + ty * 8 + b;
        float ps = acc[b].x * av.x + acc[b].y * av.y + acc[b].z * av.z + acc[b].w * av.w;
        float pd = acc[b].x * dv.x + acc[b].y * dv.y + acc[b].z * dv.z + acc[b].w * dv.w;
#pragma unroll
        for (int off = 4; off > 0; off >>= 1) {
            ps += __shfl_xor_sync(0xffffffffu, ps, off);
            pd += __shfl_xor_sync(0xffffffffu, pd, off);
        }
        if (gn < N) {
            g_h1h[(size_t)gn * 64 + tx * 2]     = __floats2half2_rn(acc[b].x, acc[b].y);
            g_h1h[(size_t)gn * 64 + tx * 2 + 1] = __floats2half2_rn(acc[b].z, acc[b].w);
            if ((tx & 7) == 0) {
                asf[gn * 4 + h] = ps;
                adf[gn * 4 + h] = pd;
            }
        }
    }
}

// ---------------- layer 1: fused softmax + aggregation + bias + relu ----------------
// warp per node; lane owns channels {4l..4l+3} (head lane>>3); 8 edges per group.
__global__ void agg1_kernel(const float* __restrict__ b1, int N) {
    int n = (blockIdx.x * blockDim.x + threadIdx.x) >> 5;
    int lane = threadIdx.x & 31;
    if (n >= N) return;
    const float* asf = (const float*)g_as1;
    const float* adf = (const float*)g_ad1;
    int e = lane & 7;
    int h = lane >> 3;
    int base = lane & 24;
    float adh = adf[(size_t)n * 4 + h];
    const int2* h1p = (const int2*)g_h1h;

    int beg = g_rowptr[n], end = g_rowptr[n + 1];
    float4 acc = make_float4(0.f, 0.f, 0.f, 0.f);
    float dsum = 0.f;

    for (int i = beg; i < end; i += 8) {
        int cnt = end - i;
        int s_l = 0;
        if (lane < 8 && lane < cnt) s_l = g_csrc[i + lane];
        int se = __shfl_sync(0xffffffffu, s_l, e);

        float w = 0.f;
        if (e < cnt) w = __expf(lrelu(asf[(size_t)se * 4 + h] + adh));
        dsum += w;

#pragma unroll
        for (int EI = 0; EI < 8; EI++) {
            if (EI >= cnt) break;  // warp-uniform
            int   sE = __shfl_sync(0xffffffffu, s_l, EI);
            float wE = __shfl_sync(0xffffffffu, w, base + EI);
            int2 p = h1p[(size_t)sE * 32 + lane];
            float2 f0 = __half22float2(*(__half2*)&p.x);
            float2 f1 = __half22float2(*(__half2*)&p.y);
            acc.x += wE * f0.x;
            acc.y += wE * f0.y;
            acc.z += wE * f1.x;
            acc.w += wE * f1.y;
        }
    }

    // per-head denominator: sum across the 8 edge-slot lanes of this head group
    dsum += __shfl_xor_sync(0xffffffffu, dsum, 1);
    dsum += __shfl_xor_sync(0xffffffffu, dsum, 2);
    dsum += __shfl_xor_sync(0xffffffffu, dsum, 4);
    float r = 1.f / dsum;

    float4 bv = ((const float4*)b1)[lane];
    float o0 = fmaxf(acc.x * r + bv.x, 0.f);
    float o1 = fmaxf(acc.y * r + bv.y, 0.f);
    float o2 = fmaxf(acc.z * r + bv.z, 0.f);
    float o3 = fmaxf(acc.w * r + bv.w, 0.f);
    int2 st;
    *(__half2*)&st.x = __floats2half2_rn(o0, o1);
    *(__half2*)&st.y = __floats2half2_rn(o2, o3);
    ((int2*)g_h1ah)[(size_t)n * 32 + lane] = st;
}

// ---------------- GEMM2: h2[N,32] = h1a[N,128](half) @ W2[128,32] + coef epilogue ----------------
__global__ void __launch_bounds__(128) gemm2_kernel(
    const float* __restrict__ W,
    const float* __restrict__ a_src, const float* __restrict__ a_dst, int N) {
    __shared__ float   Ws[128 * 32];
    __shared__ __half2 xs[32 * 68];   // 64 half2 per row, padded stride 68

    int t  = threadIdx.x;
    int tx = t & 7;
    int ty = t >> 3;
    int n0 = blockIdx.x * 32;

#pragma unroll
    for (int r = 0; r < 8; r++)
        ((float4*)Ws)[t + r * 128] = ((const float4*)W)[t + r * 128];
#pragma unroll
    for (int r = 0; r < 8; r++) {
        int f = t + r * 128;
        int node = f >> 5;
        int part = f & 31;
        int gn = n0 + node;
        int2 v = make_int2(0, 0);
        if (gn < N) v = ((const int2*)g_h1ah)[(size_t)gn * 32 + part];
        *(int2*)&xs[node * 68 + part * 2] = v;
    }
    __syncthreads();

    float4 acc[2];
    acc[0] = make_float4(0.f, 0.f, 0.f, 0.f);
    acc[1] = make_float4(0.f, 0.f, 0.f, 0.f);

#pragma unroll 4
    for (int k0 = 0; k0 < 128; k0 += 4) {
        float4 w0 = *(const float4*)&Ws[(k0 + 0) * 32 + tx * 4];
        float4 w1 = *(const float4*)&Ws[(k0 + 1) * 32 + tx * 4];
        float4 w2 = *(const float4*)&Ws[(k0 + 2) * 32 + tx * 4];
        float4 w3 = *(const float4*)&Ws[(k0 + 3) * 32 + tx * 4];
#pragma unroll
        for (int b = 0; b < 2; b++) {
            int2 p = *(const int2*)&xs[(ty * 2 + b) * 68 + (k0 >> 1)];
            float2 x01 = __half22float2(*(__half2*)&p.x);
            float2 x23 = __half22float2(*(__half2*)&p.y);
            acc[b].x += x01.x * w0.x + x01.y * w1.x + x23.x * w2.x + x23.y * w3.x;
            acc[b].y += x01.x * w0.y + x01.y * w1.y + x23.x * w2.y + x23.y * w3.y;
            acc[b].z += x01.x * w0.z + x01.y * w1.z + x23.x * w2.z + x23.y * w3.z;
            acc[b].w += x01.x * w0.w + x01.y * w1.w + x23.x * w2.w + x23.y * w3.w;
        }
    }

    float4 av = ((const float4*)a_src)[tx];
    float4 dv = ((const float4*)a_dst)[tx];
#pragma unroll
    for (int b = 0; b < 2; b++) {
        int gn = n0 + ty * 2 + b;
        float ps = acc[b].x * av.x + acc[b].y * av.y + acc[b].z * av.z + acc[b].w * av.w;
        float pd = acc[b].x * dv.x + acc[b].y * dv.y + acc[b].z * dv.z + acc[b].w * dv.w;
#pragma unroll
        for (int off = 4; off > 0; off >>= 1) {
            ps += __shfl_xor_sync(0xffffffffu, ps, off);
            pd += __shfl_xor_sync(0xffffffffu, pd, off);
        }
        if (gn < N) {
            int2 st;
            *(__half2*)&st.x = __floats2half2_rn(acc[b].x, acc[b].y);
            *(__half2*)&st.y = __floats2half2_rn(acc[b].z, acc[b].w);
            ((int2*)g_h2h)[(size_t)gn * 8 + tx] = st;
            if (tx == 0) {
                g_as2[gn] = ps;
                g_ad2[gn] = pd;
            }
        }
    }
}

// ---------------- layer 2: fused softmax + aggregation + bias + relu + final linear ----------------
// warp per node; lane owns channels {2(lane&15), 2(lane&15)+1} (duplicated across half-warps).
__global__ void agg2_kernel(const float* __restrict__ b2, const float* __restrict__ Wl,
                            const float* __restrict__ bl, float* __restrict__ out, int N) {
    int n = (blockIdx.x * blockDim.x + threadIdx.x) >> 5;
    int lane = threadIdx.x & 31;
    if (n >= N) return;
    float ad = g_ad2[n];
    int e = lane & 7;
    int base = lane & 24;
    int c = lane & 15;
    int beg = g_rowptr[n], end = g_rowptr[n + 1];

    float2 acc = make_float2(0.f, 0.f);
    float ds = 0.f;

    for (int i = beg; i < end; i += 8) {
        int cnt = end - i;
        int s_l = 0;
        if (lane < 8 && lane < cnt) s_l = g_csrc[i + lane];
        int se = __shfl_sync(0xffffffffu, s_l, e);

        float w = 0.f;
        if (e < cnt) w = __expf(lrelu(g_as2[se] + ad));
        ds += w;

#pragma unroll
        for (int EI = 0; EI < 8; EI++) {
            if (EI >= cnt) break;  // warp-uniform
            int   sE = __shfl_sync(0xffffffffu, s_l, EI);
            float wE = __shfl_sync(0xffffffffu, w, base + EI);
            float2 f = __half22float2(g_h2h[(size_t)sE * 16 + c]);
            acc.x += wE * f.x;
            acc.y += wE * f.y;
        }
    }

    // each group of 8 lanes computed all 8 weights -> xor reduce within group = full denom
    ds += __shfl_xor_sync(0xffffffffu, ds, 1);
    ds += __shfl_xor_sync(0xffffffffu, ds, 2);
    ds += __shfl_xor_sync(0xffffffffu, ds, 4);
    float r = 1.f / ds;

    float v = fmaxf(acc.x * r + b2[2 * c],     0.f) * Wl[2 * c]
            + fmaxf(acc.y * r + b2[2 * c + 1], 0.f) * Wl[2 * c + 1];
#pragma unroll
    for (int off = 16; off > 0; off >>= 1) v += __shfl_xor_sync(0xffffffffu, v, off);
    if (lane == 0) out[n] = v * 0.5f + bl[0];  // channels duplicated across half-warps
}

// ---------------- launch ----------------
extern "C" void kernel_launch(void* const* d_in, const int* in_sizes, int n_in,
                              void* d_out, int out_size) {
    const float* x    = (const float*)d_in[0];
    const int*   ei   = (const int*)d_in[1];
    const float* W1   = (const float*)d_in[3];
    const float* as1w = (const float*)d_in[4];
    const float* ad1w = (const float*)d_in[5];
    const float* b1   = (const float*)d_in[6];
    const float* W2   = (const float*)d_in[7];
    const float* as2w = (const float*)d_in[8];
    const float* ad2w = (const float*)d_in[9];
    const float* b2   = (const float*)d_in[10];
    const float* Wl   = (const float*)d_in[11];
    const float* bl   = (const float*)d_in[12];
    float* out = (float*)d_out;

    int N = in_sizes[0] / 64;
    int E = in_sizes[1] / 2;

    int nb = (N + 255) / 256;
    int eb = (E + 255) / 256;
    int wb = (N + 7) / 8;  // warp-per-node, 8 warps per 256-thread block

    // CSR build
    initdeg_kernel<<<nb, 256>>>(N);
    hist_kernel<<<eb, 256>>>(ei, E);
    scan_kernel<<<1, 1024>>>(N);
    fillself_kernel<<<nb, 256>>>(N);
    filledge_kernel<<<eb, 256>>>(ei, E);

    // layer 1
    gemm1_kernel<<<(N + 63) / 64, 256>>>(x, W1, as1w, ad1w, N);
    agg1_kernel<<<wb, 256>>>(b1, N);

    // layer 2
    gemm2_kernel<<<(N + 31) / 32, 128>>>(W2, as2w, ad2w, N);
    agg2_kernel<<<wb, 256>>>(b2, Wl, bl, out, N);
}

// round 6
// speedup vs baseline: 1.4796x; 1.1268x over previous
#include <cuda_runtime.h>
#include <cuda_fp16.h>

#define NMAX 100000
#define EMAX 1600000
#define TMAX (NMAX + EMAX)

// ---------------- scratch (static device globals; no allocation) ----------------
__device__ int    g_deg[NMAX];
__device__ int    g_rowptr[NMAX + 1];
__device__ int    g_cursor[NMAX];
__device__ int    g_csrc[TMAX];

__device__ __half2 g_h1h[NMAX * 64];   // layer1 features (x@W1), 128ch as 64 half2
__device__ float4  g_as1[NMAX];        // h . a_src per node, 4 heads
__device__ float4  g_ad1[NMAX];        // h . a_dst per node, 4 heads

__device__ __half2 g_h1ah[NMAX * 64];  // relu(agg1 + b1): layer2 input, half2
__device__ __half2 g_h2h[NMAX * 16];   // layer2 pre-attention features, 32ch half2
__device__ float   g_as2[NMAX];
__device__ float   g_ad2[NMAX];

__device__ __forceinline__ float lrelu(float x) { return x > 0.f ? x : 0.2f * x; }

__device__ __forceinline__ void mma16816(float* d, unsigned a0, unsigned a1,
                                         unsigned a2, unsigned a3,
                                         unsigned b0, unsigned b1) {
    asm volatile(
        "mma.sync.aligned.m16n8k16.row.col.f32.f16.f16.f32 "
        "{%0,%1,%2,%3}, {%4,%5,%6,%7}, {%8,%9}, {%0,%1,%2,%3};\n"
        : "+f"(d[0]), "+f"(d[1]), "+f"(d[2]), "+f"(d[3])
        : "r"(a0), "r"(a1), "r"(a2), "r"(a3), "r"(b0), "r"(b1));
}

// ---------------- CSR build ----------------
__global__ void initdeg_kernel(int N) {
    int n = blockIdx.x * blockDim.x + threadIdx.x;
    if (n < N) g_deg[n] = 1;  // self loop
}

__global__ void hist_kernel(const int* __restrict__ ei, int E) {
    int e = blockIdx.x * blockDim.x + threadIdx.x;
    if (e < E) atomicAdd(&g_deg[ei[E + e]], 1);
}

__global__ void scan_kernel(int N) {
    __shared__ int s[1024];
    int t = threadIdx.x;
    int chunk = (N + 1023) >> 10;
    int lo = t * chunk;
    int hi = min(lo + chunk, N);
    int sum = 0;
    for (int i = lo; i < hi; i++) sum += g_deg[i];
    s[t] = sum;
    __syncthreads();
    for (int off = 1; off < 1024; off <<= 1) {
        int v = (t >= off) ? s[t - off] : 0;
        __syncthreads();
        s[t] += v;
        __syncthreads();
    }
    int run = (t > 0) ? s[t - 1] : 0;
    for (int i = lo; i < hi; i++) { g_rowptr[i] = run; run += g_deg[i]; }
    if (t == 1023) g_rowptr[N] = s[1023];
}

__global__ void fillself_kernel(int N) {
    int n = blockIdx.x * blockDim.x + threadIdx.x;
    if (n < N) {
        int r = g_rowptr[n];
        g_csrc[r] = n;         // self loop first
        g_cursor[n] = r + 1;
    }
}

__global__ void filledge_kernel(const int* __restrict__ ei, int E) {
    int e = blockIdx.x * blockDim.x + threadIdx.x;
    if (e < E) {
        int dst = ei[E + e];
        int pos = atomicAdd(&g_cursor[dst], 1);
        g_csrc[pos] = ei[e];
    }
}

// ---------------- GEMM1 (tensor): h1[N,128] = X[N,64] @ W1[64,128] + coef epilogue ----
// 256 thr = 8 warps. 64 nodes/block. warp w: rows (w&3)*16..+15, cols (w>>2)*64..+63.
__global__ void __launch_bounds__(256) gemm1_kernel(
    const float* __restrict__ X, const float* __restrict__ W,
    const float* __restrict__ a_src, const float* __restrict__ a_dst, int N) {
    __shared__ __half xs[64 * 72];    // [node][k], stride 72
    __shared__ __half ws[128 * 72];   // W transposed: [n][k], stride 72

    int t = threadIdx.x;
    int lane = t & 31;
    int w = t >> 5;
    int gid = lane >> 2;
    int tig = lane & 3;
    int n0 = blockIdx.x * 64;

#pragma unroll
    for (int r = 0; r < 4; r++) {
        int f = t + r * 256;
        int node = f >> 4;
        int kk = (f & 15) << 2;
        int gn = n0 + node;
        float4 v = make_float4(0.f, 0.f, 0.f, 0.f);
        if (gn < N) v = *(const float4*)&X[(size_t)gn * 64 + kk];
        __half2* dst = (__half2*)&xs[node * 72 + kk];
        dst[0] = __floats2half2_rn(v.x, v.y);
        dst[1] = __floats2half2_rn(v.z, v.w);
    }
#pragma unroll
    for (int r = 0; r < 32; r++) {
        int f = t + r * 256;            // k*128 + n
        int k = f >> 7;
        int n = f & 127;
        ws[n * 72 + k] = __float2half(W[f]);
    }
    __syncthreads();

    int m0 = (w & 3) * 16;
    int nbase = (w >> 2) * 64;
    float acc[8][4];
#pragma unroll
    for (int nf = 0; nf < 8; nf++)
#pragma unroll
        for (int i = 0; i < 4; i++) acc[nf][i] = 0.f;

#pragma unroll
    for (int ks = 0; ks < 4; ks++) {
        int k0 = ks * 16 + 2 * tig;
        unsigned a0 = *(const unsigned*)&xs[(m0 + gid) * 72 + k0];
        unsigned a1 = *(const unsigned*)&xs[(m0 + gid + 8) * 72 + k0];
        unsigned a2 = *(const unsigned*)&xs[(m0 + gid) * 72 + k0 + 8];
        unsigned a3 = *(const unsigned*)&xs[(m0 + gid + 8) * 72 + k0 + 8];
#pragma unroll
        for (int nf = 0; nf < 8; nf++) {
            int nn = nbase + nf * 8 + gid;
            unsigned b0 = *(const unsigned*)&ws[nn * 72 + k0];
            unsigned b1 = *(const unsigned*)&ws[nn * 72 + k0 + 8];
            mma16816(acc[nf], a0, a1, a2, a3, b0, b1);
        }
    }

    // epilogue: store h1 (half2) + fused a_src/a_dst dots
    int gn0 = n0 + m0 + gid;
    int gn1 = gn0 + 8;
    float psA0 = 0.f, psA1 = 0.f, pdA0 = 0.f, pdA1 = 0.f;
    float psB0 = 0.f, psB1 = 0.f, pdB0 = 0.f, pdB1 = 0.f;
#pragma unroll
    for (int nf = 0; nf < 8; nf++) {
        int c = nbase + nf * 8 + 2 * tig;
        float avx = a_src[c], avy = a_src[c + 1];
        float dvx = a_dst[c], dvy = a_dst[c + 1];
        float p0s = acc[nf][0] * avx + acc[nf][1] * avy;
        float p1s = acc[nf][2] * avx + acc[nf][3] * avy;
        float p0d = acc[nf][0] * dvx + acc[nf][1] * dvy;
        float p1d = acc[nf][2] * dvx + acc[nf][3] * dvy;
        if (nf < 4) { psA0 += p0s; psA1 += p1s; pdA0 += p0d; pdA1 += p1d; }
        else        { psB0 += p0s; psB1 += p1s; pdB0 += p0d; pdB1 += p1d; }
        if (gn0 < N) g_h1h[(size_t)gn0 * 64 + (c >> 1)] = __floats2half2_rn(acc[nf][0], acc[nf][1]);
        if (gn1 < N) g_h1h[(size_t)gn1 * 64 + (c >> 1)] = __floats2half2_rn(acc[nf][2], acc[nf][3]);
    }
#pragma unroll
    for (int off = 1; off <= 2; off <<= 1) {
        psA0 += __shfl_xor_sync(0xffffffffu, psA0, off);
        psA1 += __shfl_xor_sync(0xffffffffu, psA1, off);
        pdA0 += __shfl_xor_sync(0xffffffffu, pdA0, off);
        pdA1 += __shfl_xor_sync(0xffffffffu, pdA1, off);
        psB0 += __shfl_xor_sync(0xffffffffu, psB0, off);
        psB1 += __shfl_xor_sync(0xffffffffu, psB1, off);
        pdB0 += __shfl_xor_sync(0xffffffffu, pdB0, off);
        pdB1 += __shfl_xor_sync(0xffffffffu, pdB1, off);
    }
    if (tig == 0) {
        float* asf = (float*)g_as1;
        float* adf = (float*)g_ad1;
        int hA = nbase >> 5;       // 0 or 2
        if (gn0 < N) {
            asf[gn0 * 4 + hA] = psA0;  asf[gn0 * 4 + hA + 1] = psB0;
            adf[gn0 * 4 + hA] = pdA0;  adf[gn0 * 4 + hA + 1] = pdB0;
        }
        if (gn1 < N) {
            asf[gn1 * 4 + hA] = psA1;  asf[gn1 * 4 + hA + 1] = psB1;
            adf[gn1 * 4 + hA] = pdA1;  adf[gn1 * 4 + hA + 1] = pdB1;
        }
    }
}

// ---------------- layer 1: fused softmax + aggregation + bias + relu ----------------
__global__ void agg1_kernel(const float* __restrict__ b1, int N) {
    int n = (blockIdx.x * blockDim.x + threadIdx.x) >> 5;
    int lane = threadIdx.x & 31;
    if (n >= N) return;
    const float* asf = (const float*)g_as1;
    const float* adf = (const float*)g_ad1;
    int e = lane & 7;
    int h = lane >> 3;
    int base = lane & 24;
    float adh = adf[(size_t)n * 4 + h];
    const int2* h1p = (const int2*)g_h1h;

    int beg = g_rowptr[n], end = g_rowptr[n + 1];
    float4 acc = make_float4(0.f, 0.f, 0.f, 0.f);
    float dsum = 0.f;

    for (int i = beg; i < end; i += 8) {
        int cnt = end - i;
        int s_l = 0;
        if (lane < 8 && lane < cnt) s_l = g_csrc[i + lane];
        int se = __shfl_sync(0xffffffffu, s_l, e);

        float w = 0.f;
        if (e < cnt) w = __expf(lrelu(asf[(size_t)se * 4 + h] + adh));
        dsum += w;

#pragma unroll
        for (int EI = 0; EI < 8; EI++) {
            if (EI >= cnt) break;  // warp-uniform
            int   sE = __shfl_sync(0xffffffffu, s_l, EI);
            float wE = __shfl_sync(0xffffffffu, w, base + EI);
            int2 p = h1p[(size_t)sE * 32 + lane];
            float2 f0 = __half22float2(*(__half2*)&p.x);
            float2 f1 = __half22float2(*(__half2*)&p.y);
            acc.x += wE * f0.x;
            acc.y += wE * f0.y;
            acc.z += wE * f1.x;
            acc.w += wE * f1.y;
        }
    }

    dsum += __shfl_xor_sync(0xffffffffu, dsum, 1);
    dsum += __shfl_xor_sync(0xffffffffu, dsum, 2);
    dsum += __shfl_xor_sync(0xffffffffu, dsum, 4);
    float r = 1.f / dsum;

    float4 bv = ((const float4*)b1)[lane];
    float o0 = fmaxf(acc.x * r + bv.x, 0.f);
    float o1 = fmaxf(acc.y * r + bv.y, 0.f);
    float o2 = fmaxf(acc.z * r + bv.z, 0.f);
    float o3 = fmaxf(acc.w * r + bv.w, 0.f);
    int2 st;
    *(__half2*)&st.x = __floats2half2_rn(o0, o1);
    *(__half2*)&st.y = __floats2half2_rn(o2, o3);
    ((int2*)g_h1ah)[(size_t)n * 32 + lane] = st;
}

// ---------------- GEMM2 (tensor): h2[N,32] = h1a[N,128](f16) @ W2[128,32] + coef epilogue ----
// 128 thr = 4 warps. 64 nodes/block. warp w: rows w*16..+15, all 32 cols.
__global__ void __launch_bounds__(128) gemm2_kernel(
    const float* __restrict__ W,
    const float* __restrict__ a_src, const float* __restrict__ a_dst, int N) {
    __shared__ __half xs[64 * 136];   // [node][k], stride 136
    __shared__ __half ws[32 * 136];   // W transposed: [n][k], stride 136

    int t = threadIdx.x;
    int lane = t & 31;
    int w = t >> 5;
    int gid = lane >> 2;
    int tig = lane & 3;
    int n0 = blockIdx.x * 64;

    // X rows: 128 halfs = 16 int4 each; stride 136 halfs = 17 int4
#pragma unroll
    for (int r = 0; r < 8; r++) {
        int f = t + r * 128;
        int node = f >> 4;
        int part = f & 15;
        int gn = n0 + node;
        int4 v = make_int4(0, 0, 0, 0);
        if (gn < N) v = ((const int4*)g_h1ah)[(size_t)gn * 16 + part];
        ((int4*)xs)[node * 17 + part] = v;
    }
#pragma unroll
    for (int r = 0; r < 32; r++) {
        int f = t + r * 128;            // k*32 + n
        int k = f >> 5;
        int n = f & 31;
        ws[n * 136 + k] = __float2half(W[f]);
    }
    __syncthreads();

    int m0 = w * 16;
    float acc[4][4];
#pragma unroll
    for (int nf = 0; nf < 4; nf++)
#pragma unroll
        for (int i = 0; i < 4; i++) acc[nf][i] = 0.f;

#pragma unroll
    for (int ks = 0; ks < 8; ks++) {
        int k0 = ks * 16 + 2 * tig;
        unsigned a0 = *(const unsigned*)&xs[(m0 + gid) * 136 + k0];
        unsigned a1 = *(const unsigned*)&xs[(m0 + gid + 8) * 136 + k0];
        unsigned a2 = *(const unsigned*)&xs[(m0 + gid) * 136 + k0 + 8];
        unsigned a3 = *(const unsigned*)&xs[(m0 + gid + 8) * 136 + k0 + 8];
#pragma unroll
        for (int nf = 0; nf < 4; nf++) {
            int nn = nf * 8 + gid;
            unsigned b0 = *(const unsigned*)&ws[nn * 136 + k0];
            unsigned b1 = *(const unsigned*)&ws[nn * 136 + k0 + 8];
            mma16816(acc[nf], a0, a1, a2, a3, b0, b1);
        }
    }

    int gn0 = n0 + m0 + gid;
    int gn1 = gn0 + 8;
    float ps0 = 0.f, ps1 = 0.f, pd0 = 0.f, pd1 = 0.f;
#pragma unroll
    for (int nf = 0; nf < 4; nf++) {
        int c = nf * 8 + 2 * tig;
        float avx = a_src[c], avy = a_src[c + 1];
        float dvx = a_dst[c], dvy = a_dst[c + 1];
        ps0 += acc[nf][0] * avx + acc[nf][1] * avy;
        ps1 += acc[nf][2] * avx + acc[nf][3] * avy;
        pd0 += acc[nf][0] * dvx + acc[nf][1] * dvy;
        pd1 += acc[nf][2] * dvx + acc[nf][3] * dvy;
        if (gn0 < N) g_h2h[(size_t)gn0 * 16 + (c >> 1)] = __floats2half2_rn(acc[nf][0], acc[nf][1]);
        if (gn1 < N) g_h2h[(size_t)gn1 * 16 + (c >> 1)] = __floats2half2_rn(acc[nf][2], acc[nf][3]);
    }
#pragma unroll
    for (int off = 1; off <= 2; off <<= 1) {
        ps0 += __shfl_xor_sync(0xffffffffu, ps0, off);
        ps1 += __shfl_xor_sync(0xffffffffu, ps1, off);
        pd0 += __shfl_xor_sync(0xffffffffu, pd0, off);
        pd1 += __shfl_xor_sync(0xffffffffu, pd1, off);
    }
    if (tig == 0) {
        if (gn0 < N) { g_as2[gn0] = ps0; g_ad2[gn0] = pd0; }
        if (gn1 < N) { g_as2[gn1] = ps1; g_ad2[gn1] = pd1; }
    }
}

// ---------------- layer 2: fused softmax + aggregation + bias + relu + final linear ----------------
__global__ void agg2_kernel(const float* __restrict__ b2, const float* __restrict__ Wl,
                            const float* __restrict__ bl, float* __restrict__ out, int N) {
    int n = (blockIdx.x * blockDim.x + threadIdx.x) >> 5;
    int lane = threadIdx.x & 31;
    if (n >= N) return;
    float ad = g_ad2[n];
    int e = lane & 7;
    int base = lane & 24;
    int c = lane & 15;
    int beg = g_rowptr[n], end = g_rowptr[n + 1];

    float2 acc = make_float2(0.f, 0.f);
    float ds = 0.f;

    for (int i = beg; i < end; i += 8) {
        int cnt = end - i;
        int s_l = 0;
        if (lane < 8 && lane < cnt) s_l = g_csrc[i + lane];
        int se = __shfl_sync(0xffffffffu, s_l, e);

        float w = 0.f;
        if (e < cnt) w = __expf(lrelu(g_as2[se] + ad));
        ds += w;

#pragma unroll
        for (int EI = 0; EI < 8; EI++) {
            if (EI >= cnt) break;  // warp-uniform
            int   sE = __shfl_sync(0xffffffffu, s_l, EI);
            float wE = __shfl_sync(0xffffffffu, w, base + EI);
            float2 f = __half22float2(g_h2h[(size_t)sE * 16 + c]);
            acc.x += wE * f.x;
            acc.y += wE * f.y;
        }
    }

    ds += __shfl_xor_sync(0xffffffffu, ds, 1);
    ds += __shfl_xor_sync(0xffffffffu, ds, 2);
    ds += __shfl_xor_sync(0xffffffffu, ds, 4);
    float r = 1.f / ds;

    float v = fmaxf(acc.x * r + b2[2 * c],     0.f) * Wl[2 * c]
            + fmaxf(acc.y * r + b2[2 * c + 1], 0.f) * Wl[2 * c + 1];
#pragma unroll
    for (int off = 16; off > 0; off >>= 1) v += __shfl_xor_sync(0xffffffffu, v, off);
    if (lane == 0) out[n] = v * 0.5f + bl[0];  // channels duplicated across half-warps
}

// ---------------- launch ----------------
extern "C" void kernel_launch(void* const* d_in, const int* in_sizes, int n_in,
                              void* d_out, int out_size) {
    const float* x    = (const float*)d_in[0];
    const int*   ei   = (const int*)d_in[1];
    const float* W1   = (const float*)d_in[3];
    const float* as1w = (const float*)d_in[4];
    const float* ad1w = (const float*)d_in[5];
    const float* b1   = (const float*)d_in[6];
    const float* W2   = (const float*)d_in[7];
    const float* as2w = (const float*)d_in[8];
    const float* ad2w = (const float*)d_in[9];
    const float* b2   = (const float*)d_in[10];
    const float* Wl   = (const float*)d_in[11];
    const float* bl   = (const float*)d_in[12];
    float* out = (float*)d_out;

    int N = in_sizes[0] / 64;
    int E = in_sizes[1] / 2;

    int nb = (N + 255) / 256;
    int eb = (E + 255) / 256;
    int wb = (N + 7) / 8;  // warp-per-node, 8 warps per 256-thread block

    // CSR build
    initdeg_kernel<<<nb, 256>>>(N);
    hist_kernel<<<eb, 256>>>(ei, E);
    scan_kernel<<<1, 1024>>>(N);
    fillself_kernel<<<nb, 256>>>(N);
    filledge_kernel<<<eb, 256>>>(ei, E);

    // layer 1
    gemm1_kernel<<<(N + 63) / 64, 256>>>(x, W1, as1w, ad1w, N);
    agg1_kernel<<<wb, 256>>>(b1, N);

    // layer 2
    gemm2_kernel<<<(N + 63) / 64, 128>>>(W2, as2w, ad2w, N);
    agg2_kernel<<<wb, 256>>>(b2, Wl, bl, out, N);
}

// round 8
// speedup vs baseline: 1.6263x; 1.0991x over previous
#include <cuda_runtime.h>
#include <cuda_fp16.h>

#define NMAX 100000
#define EMAX 1600000
#define TMAX (NMAX + EMAX)

// ---------------- scratch (static device globals; no allocation) ----------------
__device__ int    g_deg[NMAX];
__device__ int    g_rowptr[NMAX + 1];
__device__ int    g_cursor[NMAX];
__device__ int    g_csrc[TMAX];

__device__ __half2 g_h1h[NMAX * 64];   // layer1 features (x@W1), 128ch as 64 half2
__device__ float4  g_as1[NMAX];        // h . a_src per node, 4 heads
__device__ float4  g_ad1[NMAX];        // h . a_dst per node, 4 heads
__device__ float4  g_alpha1[TMAX];     // unnormalized softmax weight per CSR entry, 4 heads
__device__ float4  g_r1[NMAX];         // 1/denominator per node, 4 heads

__device__ __half2 g_h1ah[NMAX * 64];  // relu(agg1 + b1): layer2 input, half2
__device__ __half2 g_h2h[NMAX * 16];   // layer2 pre-attention features, 32ch half2
__device__ float   g_as2[NMAX];
__device__ float   g_ad2[NMAX];
__device__ float   g_alpha2[TMAX];
__device__ float   g_r2[NMAX];

__device__ __forceinline__ float lrelu(float x) { return x > 0.f ? x : 0.2f * x; }

__device__ __forceinline__ void mma16816(float* d, unsigned a0, unsigned a1,
                                         unsigned a2, unsigned a3,
                                         unsigned b0, unsigned b1) {
    asm volatile(
        "mma.sync.aligned.m16n8k16.row.col.f32.f16.f16.f32 "
        "{%0,%1,%2,%3}, {%4,%5,%6,%7}, {%8,%9}, {%0,%1,%2,%3};\n"
        : "+f"(d[0]), "+f"(d[1]), "+f"(d[2]), "+f"(d[3])
        : "r"(a0), "r"(a1), "r"(a2), "r"(a3), "r"(b0), "r"(b1));
}

// ---------------- CSR build ----------------
__global__ void initdeg_kernel(int N) {
    int n = blockIdx.x * blockDim.x + threadIdx.x;
    if (n < N) g_deg[n] = 1;  // self loop
}

__global__ void hist_kernel(const int* __restrict__ ei, int E) {
    int e = blockIdx.x * blockDim.x + threadIdx.x;
    if (e < E) atomicAdd(&g_deg[ei[E + e]], 1);
}

__global__ void scan_kernel(int N) {
    __shared__ int s[1024];
    int t = threadIdx.x;
    int chunk = (N + 1023) >> 10;
    int lo = t * chunk;
    int hi = min(lo + chunk, N);
    int sum = 0;
    for (int i = lo; i < hi; i++) sum += g_deg[i];
    s[t] = sum;
    __syncthreads();
    for (int off = 1; off < 1024; off <<= 1) {
        int v = (t >= off) ? s[t - off] : 0;
        __syncthreads();
        s[t] += v;
        __syncthreads();
    }
    int run = (t > 0) ? s[t - 1] : 0;
    for (int i = lo; i < hi; i++) { g_rowptr[i] = run; run += g_deg[i]; }
    if (t == 1023) g_rowptr[N] = s[1023];
}

__global__ void fillself_kernel(int N) {
    int n = blockIdx.x * blockDim.x + threadIdx.x;
    if (n < N) {
        int r = g_rowptr[n];
        g_csrc[r] = n;         // self loop first
        g_cursor[n] = r + 1;
    }
}

__global__ void filledge_kernel(const int* __restrict__ ei, int E) {
    int e = blockIdx.x * blockDim.x + threadIdx.x;
    if (e < E) {
        int dst = ei[E + e];
        int pos = atomicAdd(&g_cursor[dst], 1);
        g_csrc[pos] = ei[e];
    }
}

// ---------------- GEMM1 (tensor): h1[N,128] = X[N,64] @ W1[64,128] + coef epilogue ----
__global__ void __launch_bounds__(256) gemm1_kernel(
    const float* __restrict__ X, const float* __restrict__ W,
    const float* __restrict__ a_src, const float* __restrict__ a_dst, int N) {
    __shared__ __half xs[64 * 72];    // [node][k], stride 72
    __shared__ __half ws[128 * 72];   // W transposed: [n][k], stride 72

    int t = threadIdx.x;
    int lane = t & 31;
    int w = t >> 5;
    int gid = lane >> 2;
    int tig = lane & 3;
    int n0 = blockIdx.x * 64;

#pragma unroll
    for (int r = 0; r < 4; r++) {
        int f = t + r * 256;
        int node = f >> 4;
        int kk = (f & 15) << 2;
        int gn = n0 + node;
        float4 v = make_float4(0.f, 0.f, 0.f, 0.f);
        if (gn < N) v = *(const float4*)&X[(size_t)gn * 64 + kk];
        __half2* dst = (__half2*)&xs[node * 72 + kk];
        dst[0] = __floats2half2_rn(v.x, v.y);
        dst[1] = __floats2half2_rn(v.z, v.w);
    }
#pragma unroll
    for (int r = 0; r < 32; r++) {
        int f = t + r * 256;            // k*128 + n
        int k = f >> 7;
        int n = f & 127;
        ws[n * 72 + k] = __float2half(W[f]);
    }
    __syncthreads();

    int m0 = (w & 3) * 16;
    int nbase = (w >> 2) * 64;
    float acc[8][4];
#pragma unroll
    for (int nf = 0; nf < 8; nf++)
#pragma unroll
        for (int i = 0; i < 4; i++) acc[nf][i] = 0.f;

#pragma unroll
    for (int ks = 0; ks < 4; ks++) {
        int k0 = ks * 16 + 2 * tig;
        unsigned a0 = *(const unsigned*)&xs[(m0 + gid) * 72 + k0];
        unsigned a1 = *(const unsigned*)&xs[(m0 + gid + 8) * 72 + k0];
        unsigned a2 = *(const unsigned*)&xs[(m0 + gid) * 72 + k0 + 8];
        unsigned a3 = *(const unsigned*)&xs[(m0 + gid + 8) * 72 + k0 + 8];
#pragma unroll
        for (int nf = 0; nf < 8; nf++) {
            int nn = nbase + nf * 8 + gid;
            unsigned b0 = *(const unsigned*)&ws[nn * 72 + k0];
            unsigned b1 = *(const unsigned*)&ws[nn * 72 + k0 + 8];
            mma16816(acc[nf], a0, a1, a2, a3, b0, b1);
        }
    }

    int gn0 = n0 + m0 + gid;
    int gn1 = gn0 + 8;
    float psA0 = 0.f, psA1 = 0.f, pdA0 = 0.f, pdA1 = 0.f;
    float psB0 = 0.f, psB1 = 0.f, pdB0 = 0.f, pdB1 = 0.f;
#pragma unroll
    for (int nf = 0; nf < 8; nf++) {
        int c = nbase + nf * 8 + 2 * tig;
        float avx = a_src[c], avy = a_src[c + 1];
        float dvx = a_dst[c], dvy = a_dst[c + 1];
        float p0s = acc[nf][0] * avx + acc[nf][1] * avy;
        float p1s = acc[nf][2] * avx + acc[nf][3] * avy;
        float p0d = acc[nf][0] * dvx + acc[nf][1] * dvy;
        float p1d = acc[nf][2] * dvx + acc[nf][3] * dvy;
        if (nf < 4) { psA0 += p0s; psA1 += p1s; pdA0 += p0d; pdA1 += p1d; }
        else        { psB0 += p0s; psB1 += p1s; pdB0 += p0d; pdB1 += p1d; }
        if (gn0 < N) g_h1h[(size_t)gn0 * 64 + (c >> 1)] = __floats2half2_rn(acc[nf][0], acc[nf][1]);
        if (gn1 < N) g_h1h[(size_t)gn1 * 64 + (c >> 1)] = __floats2half2_rn(acc[nf][2], acc[nf][3]);
    }
#pragma unroll
    for (int off = 1; off <= 2; off <<= 1) {
        psA0 += __shfl_xor_sync(0xffffffffu, psA0, off);
        psA1 += __shfl_xor_sync(0xffffffffu, psA1, off);
        pdA0 += __shfl_xor_sync(0xffffffffu, pdA0, off);
        pdA1 += __shfl_xor_sync(0xffffffffu, pdA1, off);
        psB0 += __shfl_xor_sync(0xffffffffu, psB0, off);
        psB1 += __shfl_xor_sync(0xffffffffu, psB1, off);
        pdB0 += __shfl_xor_sync(0xffffffffu, pdB0, off);
        pdB1 += __shfl_xor_sync(0xffffffffu, pdB1, off);
    }
    if (tig == 0) {
        float* asf = (float*)g_as1;
        float* adf = (float*)g_ad1;
        int hA = nbase >> 5;       // 0 or 2
        if (gn0 < N) {
            asf[gn0 * 4 + hA] = psA0;  asf[gn0 * 4 + hA + 1] = psB0;
            adf[gn0 * 4 + hA] = pdA0;  adf[gn0 * 4 + hA + 1] = pdB0;
        }
        if (gn1 < N) {
            asf[gn1 * 4 + hA] = psA1;  asf[gn1 * 4 + hA + 1] = psB1;
            adf[gn1 * 4 + hA] = pdA1;  adf[gn1 * 4 + hA + 1] = pdB1;
        }
    }
}

// ---------------- layer 1: per-edge unnormalized alpha + per-node denominators ----------------
__global__ void alpha1_kernel(int N) {
    int n = (blockIdx.x * blockDim.x + threadIdx.x) >> 5;
    int lane = threadIdx.x & 31;
    if (n >= N) return;
    float4 ad = g_ad1[n];
    int beg = g_rowptr[n], end = g_rowptr[n + 1];
    float4 ds = make_float4(0.f, 0.f, 0.f, 0.f);
    for (int i = beg + lane; i < end; i += 32) {
        int s = g_csrc[i];
        float4 as = g_as1[s];
        float4 w;
        w.x = __expf(lrelu(as.x + ad.x));
        w.y = __expf(lrelu(as.y + ad.y));
        w.z = __expf(lrelu(as.z + ad.z));
        w.w = __expf(lrelu(as.w + ad.w));
        g_alpha1[i] = w;
        ds.x += w.x; ds.y += w.y; ds.z += w.z; ds.w += w.w;
    }
#pragma unroll
    for (int off = 16; off > 0; off >>= 1) {
        ds.x += __shfl_xor_sync(0xffffffffu, ds.x, off);
        ds.y += __shfl_xor_sync(0xffffffffu, ds.y, off);
        ds.z += __shfl_xor_sync(0xffffffffu, ds.z, off);
        ds.w += __shfl_xor_sync(0xffffffffu, ds.w, off);
    }
    if (lane == 0)
        g_r1[n] = make_float4(1.f / ds.x, 1.f / ds.y, 1.f / ds.z, 1.f / ds.w);
}

// ---------------- layer 1: aggregation + bias + relu (alpha precomputed) ----------------
__global__ void agg1_kernel(const float* __restrict__ b1, int N) {
    int n = (blockIdx.x * blockDim.x + threadIdx.x) >> 5;
    int lane = threadIdx.x & 31;
    if (n >= N) return;
    int h = lane >> 3;
    const float* af = (const float*)g_alpha1;
    const int2* h1p = (const int2*)g_h1h;

    int beg = g_rowptr[n], end = g_rowptr[n + 1];
    float4 acc = make_float4(0.f, 0.f, 0.f, 0.f);

    int i = beg;
    for (; i + 4 <= end; i += 4) {
        int s0 = g_csrc[i], s1 = g_csrc[i + 1], s2 = g_csrc[i + 2], s3 = g_csrc[i + 3];
        float w0 = af[(size_t)(i + 0) * 4 + h];
        float w1 = af[(size_t)(i + 1) * 4 + h];
        float w2 = af[(size_t)(i + 2) * 4 + h];
        float w3 = af[(size_t)(i + 3) * 4 + h];
        int2 p0 = h1p[(size_t)s0 * 32 + lane];
        int2 p1 = h1p[(size_t)s1 * 32 + lane];
        int2 p2 = h1p[(size_t)s2 * 32 + lane];
        int2 p3 = h1p[(size_t)s3 * 32 + lane];
        float2 f;
        f = __half22float2(*(__half2*)&p0.x); acc.x += w0 * f.x; acc.y += w0 * f.y;
        f = __half22float2(*(__half2*)&p0.y); acc.z += w0 * f.x; acc.w += w0 * f.y;
        f = __half22float2(*(__half2*)&p1.x); acc.x += w1 * f.x; acc.y += w1 * f.y;
        f = __half22float2(*(__half2*)&p1.y); acc.z += w1 * f.x; acc.w += w1 * f.y;
        f = __half22float2(*(__half2*)&p2.x); acc.x += w2 * f.x; acc.y += w2 * f.y;
        f = __half22float2(*(__half2*)&p2.y); acc.z += w2 * f.x; acc.w += w2 * f.y;
        f = __half22float2(*(__half2*)&p3.x); acc.x += w3 * f.x; acc.y += w3 * f.y;
        f = __half22float2(*(__half2*)&p3.y); acc.z += w3 * f.x; acc.w += w3 * f.y;
    }
    for (; i < end; i++) {
        int s = g_csrc[i];
        float w0 = af[(size_t)i * 4 + h];
        int2 p = h1p[(size_t)s * 32 + lane];
        float2 f;
        f = __half22float2(*(__half2*)&p.x); acc.x += w0 * f.x; acc.y += w0 * f.y;
        f = __half22float2(*(__half2*)&p.y); acc.z += w0 * f.x; acc.w += w0 * f.y;
    }

    float r = ((const float*)g_r1)[(size_t)n * 4 + h];
    float4 bv = ((const float4*)b1)[lane];
    float o0 = fmaxf(acc.x * r + bv.x, 0.f);
    float o1 = fmaxf(acc.y * r + bv.y, 0.f);
    float o2 = fmaxf(acc.z * r + bv.z, 0.f);
    float o3 = fmaxf(acc.w * r + bv.w, 0.f);
    int2 st;
    *(__half2*)&st.x = __floats2half2_rn(o0, o1);
    *(__half2*)&st.y = __floats2half2_rn(o2, o3);
    ((int2*)g_h1ah)[(size_t)n * 32 + lane] = st;
}

// ---------------- GEMM2 (tensor): h2[N,32] = h1a[N,128](f16) @ W2[128,32] + coef epilogue ----
__global__ void __launch_bounds__(128) gemm2_kernel(
    const float* __restrict__ W,
    const float* __restrict__ a_src, const float* __restrict__ a_dst, int N) {
    __shared__ __half xs[64 * 136];   // [node][k], stride 136
    __shared__ __half ws[32 * 136];   // W transposed: [n][k], stride 136

    int t = threadIdx.x;
    int lane = t & 31;
    int w = t >> 5;
    int gid = lane >> 2;
    int tig = lane & 3;
    int n0 = blockIdx.x * 64;

#pragma unroll
    for (int r = 0; r < 8; r++) {
        int f = t + r * 128;
        int node = f >> 4;
        int part = f & 15;
        int gn = n0 + node;
        int4 v = make_int4(0, 0, 0, 0);
        if (gn < N) v = ((const int4*)g_h1ah)[(size_t)gn * 16 + part];
        ((int4*)xs)[node * 17 + part] = v;
    }
#pragma unroll
    for (int r = 0; r < 32; r++) {
        int f = t + r * 128;            // k*32 + n
        int k = f >> 5;
        int n = f & 31;
        ws[n * 136 + k] = __float2half(W[f]);
    }
    __syncthreads();

    int m0 = w * 16;
    float acc[4][4];
#pragma unroll
    for (int nf = 0; nf < 4; nf++)
#pragma unroll
        for (int i = 0; i < 4; i++) acc[nf][i] = 0.f;

#pragma unroll
    for (int ks = 0; ks < 8; ks++) {
        int k0 = ks * 16 + 2 * tig;
        unsigned a0 = *(const unsigned*)&xs[(m0 + gid) * 136 + k0];
        unsigned a1 = *(const unsigned*)&xs[(m0 + gid + 8) * 136 + k0];
        unsigned a2 = *(const unsigned*)&xs[(m0 + gid) * 136 + k0 + 8];
        unsigned a3 = *(const unsigned*)&xs[(m0 + gid + 8) * 136 + k0 + 8];
#pragma unroll
        for (int nf = 0; nf < 4; nf++) {
            int nn = nf * 8 + gid;
            unsigned b0 = *(const unsigned*)&ws[nn * 136 + k0];
            unsigned b1 = *(const unsigned*)&ws[nn * 136 + k0 + 8];
            mma16816(acc[nf], a0, a1, a2, a3, b0, b1);
        }
    }

    int gn0 = n0 + m0 + gid;
    int gn1 = gn0 + 8;
    float ps0 = 0.f, ps1 = 0.f, pd0 = 0.f, pd1 = 0.f;
#pragma unroll
    for (int nf = 0; nf < 4; nf++) {
        int c = nf * 8 + 2 * tig;
        float avx = a_src[c], avy = a_src[c + 1];
        float dvx = a_dst[c], dvy = a_dst[c + 1];
        ps0 += acc[nf][0] * avx + acc[nf][1] * avy;
        ps1 += acc[nf][2] * avx + acc[nf][3] * avy;
        pd0 += acc[nf][0] * dvx + acc[nf][1] * dvy;
        pd1 += acc[nf][2] * dvx + acc[nf][3] * dvy;
        if (gn0 < N) g_h2h[(size_t)gn0 * 16 + (c >> 1)] = __floats2half2_rn(acc[nf][0], acc[nf][1]);
        if (gn1 < N) g_h2h[(size_t)gn1 * 16 + (c >> 1)] = __floats2half2_rn(acc[nf][2], acc[nf][3]);
    }
#pragma unroll
    for (int off = 1; off <= 2; off <<= 1) {
        ps0 += __shfl_xor_sync(0xffffffffu, ps0, off);
        ps1 += __shfl_xor_sync(0xffffffffu, ps1, off);
        pd0 += __shfl_xor_sync(0xffffffffu, pd0, off);
        pd1 += __shfl_xor_sync(0xffffffffu, pd1, off);
    }
    if (tig == 0) {
        if (gn0 < N) { g_as2[gn0] = ps0; g_ad2[gn0] = pd0; }
        if (gn1 < N) { g_as2[gn1] = ps1; g_ad2[gn1] = pd1; }
    }
}

// ---------------- layer 2: per-edge alpha + denominators ----------------
__global__ void alpha2_kernel(int N) {
    int n = (blockIdx.x * blockDim.x + threadIdx.x) >> 5;
    int lane = threadIdx.x & 31;
    if (n >= N) return;
    float ad = g_ad2[n];
    int beg = g_rowptr[n], end = g_rowptr[n + 1];
    float ds = 0.f;
    for (int i = beg + lane; i < end; i += 32) {
        float w = __expf(lrelu(g_as2[g_csrc[i]] + ad));
        g_alpha2[i] = w;
        ds += w;
    }
#pragma unroll
    for (int off = 16; off > 0; off >>= 1) ds += __shfl_xor_sync(0xffffffffu, ds, off);
    if (lane == 0) g_r2[n] = 1.f / ds;
}

// ---------------- layer 2: aggregation + bias + relu + final linear ----------------
// warp per node; half-warp per edge (2 edges/iteration), lane owns channels {2c,2c+1}.
__global__ void agg2_kernel(const float* __restrict__ b2, const float* __restrict__ Wl,
                            const float* __restrict__ bl, float* __restrict__ out, int N) {
    int n = (blockIdx.x * blockDim.x + threadIdx.x) >> 5;
    int lane = threadIdx.x & 31;
    if (n >= N) return;
    int half = lane >> 4;
    int c = lane & 15;
    int beg = g_rowptr[n], end = g_rowptr[n + 1];

    float2 acc = make_float2(0.f, 0.f);

    int i = beg;
    for (; i + 2 <= end; i += 2) {
        int ii = i + half;
        int s = g_csrc[ii];
        float w = g_alpha2[ii];
        float2 f = __half22float2(g_h2h[(size_t)s * 16 + c]);
        acc.x += w * f.x;
        acc.y += w * f.y;
    }
    if (i < end && half == 0) {
        int s = g_csrc[i];
        float w = g_alpha2[i];
        float2 f = __half22float2(g_h2h[(size_t)s * 16 + c]);
        acc.x += w * f.x;
        acc.y += w * f.y;
    }

    // combine halves: lanes c and c+16 hold partial sums of same channels
    acc.x += __shfl_xor_sync(0xffffffffu, acc.x, 16);
    acc.y += __shfl_xor_sync(0xffffffffu, acc.y, 16);

    float r = g_r2[n];
    float v = fmaxf(acc.x * r + b2[2 * c],     0.f) * Wl[2 * c]
            + fmaxf(acc.y * r + b2[2 * c + 1], 0.f) * Wl[2 * c + 1];
#pragma unroll
    for (int off = 1; off <= 8; off <<= 1) v += __shfl_xor_sync(0xffffffffu, v, off);
    if (lane == 0) out[n] = v + bl[0];
}

// ---------------- launch ----------------
extern "C" void kernel_launch(void* const* d_in, const int* in_sizes, int n_in,
                              void* d_out, int out_size) {
    const float* x    = (const float*)d_in[0];
    const int*   ei   = (const int*)d_in[1];
    const float* W1   = (const float*)d_in[3];
    const float* as1w = (const float*)d_in[4];
    const float* ad1w = (const float*)d_in[5];
    const float* b1   = (const float*)d_in[6];
    const float* W2   = (const float*)d_in[7];
    const float* as2w = (const float*)d_in[8];
    const float* ad2w = (const float*)d_in[9];
    const float* b2   = (const float*)d_in[10];
    const float* Wl   = (const float*)d_in[11];
    const float* bl   = (const float*)d_in[12];
    float* out = (float*)d_out;

    int N = in_sizes[0] / 64;
    int E = in_sizes[1] / 2;

    int nb = (N + 255) / 256;
    int eb = (E + 255) / 256;
    int wb = (N + 7) / 8;  // warp-per-node, 8 warps per 256-thread block

    // CSR build
    initdeg_kernel<<<nb, 256>>>(N);
    hist_kernel<<<eb, 256>>>(ei, E);
    scan_kernel<<<1, 1024>>>(N);
    fillself_kernel<<<nb, 256>>>(N);
    filledge_kernel<<<eb, 256>>>(ei, E);

    // layer 1
    gemm1_kernel<<<(N + 63) / 64, 256>>>(x, W1, as1w, ad1w, N);
    alpha1_kernel<<<wb, 256>>>(N);
    agg1_kernel<<<wb, 256>>>(b1, N);

    // layer 2
    gemm2_kernel<<<(N + 63) / 64, 128>>>(W2, as2w, ad2w, N);
    alpha2_kernel<<<wb, 256>>>(N);
    agg2_kernel<<<wb, 256>>>(b2, Wl, bl, out, N);
}